// round 6
// baseline (speedup 1.0000x reference)
#include <cuda_runtime.h>
#include <cuda_bf16.h>
#include <cstdint>
#include <math_constants.h>

#define Bq   8
#define Nq   8192
#define Sq   2048
#define Cin  512
#define NTt  128          // n-tile per CTA
#define MTt  128          // o-tile per CTA
#define KC   32           // k chunk
#define NCH  (Cin / KC)   // 16
#define NSLOT 512         // grid.x(64) * B(8)
#define Pq   (Bq * Nq)

// SMEM layout (dynamic): 3 stages of [Ahi 8K | Alo 8K | Braw fp32 18K] = 34816 B
// each; affine table (512 float2) at 104448. Epilogue reuses [0,75776).
#define STG      34816
#define B_OFF    16384
#define BROW     144      // fp32 B row stride in bytes (128 data + 16 pad)
#define AFF_OFF  104448
#define SMEM_TOT (AFF_OFF + 4096)

// ---------------- scratch (device globals) ----------------------------------
__device__ __align__(16) float g_bufA[(size_t)Bq * Nq * Cin];   // acts fp32
__device__ __align__(16) float g_bufB[(size_t)Bq * Nq * Cin];
__device__ __align__(16) __nv_bfloat16 g_Whi[655360];   // w0(256K) w1(256K) w2(128K)
__device__ __align__(16) __nv_bfloat16 g_Wlo[655360];
__device__ __align__(16) float g_p2t[(size_t)Bq * Sq * 256];
__device__ int   g_idx3[(size_t)Bq * Nq * 3];
__device__ float g_w3  [(size_t)Bq * Nq * 3];
__device__ float g_psum[512 * NSLOT];
__device__ float g_psq [512 * NSLOT];
__device__ __align__(16) float2 g_affine[3 * 512];      // (scale, shift)

// ---------------- helpers ----------------------------------------------------
__device__ __forceinline__ uint32_t smem_u32(const void* p) {
    uint32_t a;
    asm("{ .reg .u64 t; cvta.to.shared.u64 t, %1; cvt.u32.u64 %0, t; }"
        : "=r"(a) : "l"(p));
    return a;
}
#define SW64(off) ((off) ^ (((off) >> 3) & 0x30))
#define CP_ASYNC16(dst, src) \
    asm volatile("cp.async.cg.shared.global [%0], [%1], 16;" \
                 :: "r"(dst), "l"(src) : "memory")
#define CP_COMMIT()  asm volatile("cp.async.commit_group;" ::: "memory")
#define CP_WAIT(n)   asm volatile("cp.async.wait_group %0;" :: "n"(n) : "memory")

__device__ __forceinline__ void ldsm4(uint32_t* r, uint32_t addr) {
    asm volatile("ldmatrix.sync.aligned.m8n8.x4.shared.b16 {%0,%1,%2,%3}, [%4];"
                 : "=r"(r[0]), "=r"(r[1]), "=r"(r[2]), "=r"(r[3]) : "r"(addr));
}
__device__ __forceinline__ void mma16816(float* d, const uint32_t* a, const uint32_t* b) {
    asm volatile("mma.sync.aligned.m16n8k16.row.col.f32.bf16.bf16.f32 "
                 "{%0,%1,%2,%3}, {%4,%5,%6,%7}, {%8,%9}, {%0,%1,%2,%3};"
                 : "+f"(d[0]), "+f"(d[1]), "+f"(d[2]), "+f"(d[3])
                 : "r"(a[0]), "r"(a[1]), "r"(a[2]), "r"(a[3]),
                   "r"(b[0]), "r"(b[1]));
}
__device__ __forceinline__ uint32_t pack_hi(float x0, float x1) {
    __nv_bfloat162 h = __floats2bfloat162_rn(x0, x1);   // .x = x0 (lo half)
    return *(uint32_t*)&h;
}

// ---------------- transpose points2: [B,D2,S] -> [B,S,D2] -------------------
__global__ void transpose_p2(const float* __restrict__ p2) {
    __shared__ float t[32][33];
    int b  = blockIdx.z;
    int s0 = blockIdx.x * 32;
    int d0 = blockIdx.y * 32;
    int tx = threadIdx.x, ty = threadIdx.y;
    const float* src = p2 + (size_t)b * 256 * Sq;
    float*       dst = g_p2t + (size_t)b * Sq * 256;
#pragma unroll
    for (int i = 0; i < 4; i++)
        t[ty + i * 8][tx] = src[(size_t)(d0 + ty + i * 8) * Sq + s0 + tx];
    __syncthreads();
#pragma unroll
    for (int i = 0; i < 4; i++)
        dst[(size_t)(s0 + ty + i * 8) * 256 + d0 + tx] = t[tx][ty + i * 8];
}

// ---------------- 3-NN + inverse-distance weights ----------------------------
__global__ void knn3_kernel(const float* __restrict__ xyz1, const float* __restrict__ xyz2) {
    __shared__ float4 sp[Sq];
    int b   = blockIdx.y;
    int tid = threadIdx.x;
    const float* x2 = xyz2 + (size_t)b * 3 * Sq;
    for (int s = tid; s < Sq; s += 128) {
        float X = x2[s], Y = x2[Sq + s], Z = x2[2 * Sq + s];
        sp[s] = make_float4(X, Y, Z, X * X + Y * Y + Z * Z);
    }
    __syncthreads();
    int n = blockIdx.x * 128 + tid;
    const float* x1 = xyz1 + (size_t)b * 3 * Nq;
    float px = x1[n], py = x1[Nq + n], pz = x1[2 * Nq + n];
    float pn = px * px + py * py + pz * pz;
    float d1 = CUDART_INF_F, d2 = CUDART_INF_F, d3 = CUDART_INF_F;
    int   i1 = 0, i2 = 0, i3 = 0;
    for (int s = 0; s < Sq; s++) {
        float4 c = sp[s];
        float dot = px * c.x + py * c.y + pz * c.z;
        float d   = pn + c.w - 2.0f * dot;
        if (d < d3) {
            if (d < d2) {
                if (d < d1) { d3 = d2; i3 = i2; d2 = d1; i2 = i1; d1 = d; i1 = s; }
                else        { d3 = d2; i3 = i2; d2 = d;  i2 = s; }
            } else          { d3 = d;  i3 = s; }
        }
    }
    float r1 = 1.0f / (d1 + 1e-8f);
    float r2 = 1.0f / (d2 + 1e-8f);
    float r3 = 1.0f / (d3 + 1e-8f);
    float rs = r1 + r2 + r3;
    size_t base = ((size_t)b * Nq + n) * 3;
    g_idx3[base] = i1; g_idx3[base + 1] = i2; g_idx3[base + 2] = i3;
    g_w3[base] = r1 / rs; g_w3[base + 1] = r2 / rs; g_w3[base + 2] = r3 / rs;
}

// ---------------- interpolate + concat -> fp32 [B,N,512] ---------------------
__global__ void interp_concat(const float* __restrict__ p1) {
    __shared__ float t[32][33];
    int b   = blockIdx.y;
    int n0  = blockIdx.x * 32;
    int tid = threadIdx.x;
    int tx  = tid & 31, ty = tid >> 5;
    const float* p1b = p1 + (size_t)b * 256 * Nq;
    float* xo = g_bufA + (size_t)b * Nq * Cin;

    for (int ct = 0; ct < 8; ct++) {
        int c0 = ct * 32;
#pragma unroll
        for (int i = 0; i < 4; i++)
            t[ty + 8 * i][tx] = p1b[(size_t)(c0 + ty + 8 * i) * Nq + n0 + tx];
        __syncthreads();
#pragma unroll
        for (int i = 0; i < 4; i++) {
            int n = n0 + ty + 8 * i;
            xo[(size_t)n * Cin + c0 + tx] = t[tx][ty + 8 * i];
        }
        __syncthreads();
    }
    const float* p2tb = g_p2t + (size_t)b * Sq * 256;
    for (int nn = 0; nn < 32; nn++) {
        size_t base = ((size_t)b * Nq + n0 + nn) * 3;
        int   j0 = g_idx3[base], j1 = g_idx3[base + 1], j2 = g_idx3[base + 2];
        float w0 = g_w3[base], w1 = g_w3[base + 1], w2 = g_w3[base + 2];
        float v = w0 * p2tb[(size_t)j0 * 256 + tid]
                + w1 * p2tb[(size_t)j1 * 256 + tid]
                + w2 * p2tb[(size_t)j2 * 256 + tid];
        xo[(size_t)(n0 + nn) * Cin + 256 + tid] = v;
    }
}

// ---------------- weight fp32 -> bf16 hi/lo split ----------------------------
__global__ void wsplit(const float* __restrict__ w, __nv_bfloat16* __restrict__ hi,
                       __nv_bfloat16* __restrict__ lo, int n) {
    int i = blockIdx.x * 256 + threadIdx.x;
    if (i >= n) return;
    float v = w[i];
    __nv_bfloat16 h = __float2bfloat16(v);
    hi[i] = h;
    lo[i] = __float2bfloat16(v - __bfloat162float(h));
}

// ---------------- fused bf16x3 GEMM: BN+ReLU+split on the fly ----------------
// D[o,n] = sum_c W[o,c] * f(X[n,c]),  f = FUSE ? relu(a*x+d) : x  (split bf16x3)
// X is raw fp32 [B,N,512]; Y out fp32 [B,N,O] + per-CTA BN partials.
template <bool FUSE>
__global__ __launch_bounds__(256, 2)
void gemm_fused(const __nv_bfloat16* __restrict__ Whi, const __nv_bfloat16* __restrict__ Wlo,
                const float* __restrict__ Xf, float* __restrict__ Y,
                const float2* __restrict__ aff, int O) {
    extern __shared__ char smem[];
    const int tid  = threadIdx.x;
    const int wid  = tid >> 5;
    const int lane = tid & 31;
    const int b     = blockIdx.z;
    const int nBase = blockIdx.x * NTt;
    const int oBase = blockIdx.y * MTt;
    const uint32_t sb = smem_u32(smem);
    const float* Xb = Xf + (size_t)b * Nq * Cin;

    // affine table -> smem (512 float2)
    float2* affs = (float2*)(smem + AFF_OFF);
    if (FUSE) {
        affs[tid]       = aff[tid];
        affs[tid + 256] = aff[tid + 256];
    }

    const int wm0 = (wid >> 2) * 64;
    const int wn0 = (wid & 3) * 32;

    float acc[16][4];
#pragma unroll
    for (int i = 0; i < 16; i++)
#pragma unroll
        for (int j = 0; j < 4; j++) acc[i][j] = 0.0f;

    auto load_chunk = [&](int kt, int s) {
        uint32_t st = sb + s * STG;
        // A: 128 rows x 64B (hi + lo)
#pragma unroll
        for (int i = 0; i < 2; i++) {
            int idx = tid + i * 256;
            int row = idx >> 2, c = idx & 3;
            uint32_t sw = SW64((uint32_t)(row * 64 + c * 16));
            size_t g = (size_t)(oBase + row) * Cin + kt + c * 8;
            CP_ASYNC16(st + sw,        Whi + g);
            CP_ASYNC16(st + 8192 + sw, Wlo + g);
        }
        // B raw fp32: 128 rows x 128B, row stride 144B
#pragma unroll
        for (int i = 0; i < 4; i++) {
            int idx = tid + i * 256;
            int row = idx >> 3, c = idx & 7;
            CP_ASYNC16(st + B_OFF + row * BROW + c * 16,
                       Xb + (size_t)(nBase + row) * Cin + kt + c * 4);
        }
    };

    const int q  = lane >> 3, lr = lane & 7;
    const int a_row_off  = (q & 1) * 8 + lr;
    const int a_col_byte = (q >> 1) * 16;
    const int j2 = (lane & 3) * 2;        // B fragment k offset
    const int nf = lane >> 2;             // B fragment n offset (0..7)

    load_chunk(0, 0);  CP_COMMIT();
    load_chunk(KC, 1); CP_COMMIT();

    for (int k = 0; k < NCH; k++) {
        if (k < NCH - 1) { CP_WAIT(1); } else { CP_WAIT(0); }
        __syncthreads();
        if (k + 2 < NCH) {
            load_chunk((k + 2) * KC, (k + 2) % 3);
            CP_COMMIT();
        }
        const int s  = k % 3;
        const int kt = k * KC;
        char* stg = smem + s * STG;
        uint32_t aHi = sb + s * STG;
        uint32_t aLo = aHi + 8192;

#pragma unroll
        for (int kk = 0; kk < KC; kk += 16) {
            uint32_t afH[4][4], afL[4][4];
#pragma unroll
            for (int mi = 0; mi < 4; mi++) {
                int row = wm0 + mi * 16 + a_row_off;
                uint32_t sw = SW64((uint32_t)(row * 64 + kk * 2 + a_col_byte));
                ldsm4(afH[mi], aHi + sw);
                ldsm4(afL[mi], aLo + sw);
            }
            // per-thread affine params for this kk (channels kt+kk+{j2,j2+1,j2+8,j2+9})
            float a0 = 1.f, d0 = 0.f, a1 = 1.f, d1 = 0.f;
            float a2 = 1.f, d2 = 0.f, a3 = 1.f, d3 = 0.f;
            if (FUSE) {
                float2 p0 = affs[kt + kk + j2];
                float2 p1 = affs[kt + kk + j2 + 1];
                float2 p2 = affs[kt + kk + j2 + 8];
                float2 p3 = affs[kt + kk + j2 + 9];
                a0 = p0.x; d0 = p0.y; a1 = p1.x; d1 = p1.y;
                a2 = p2.x; d2 = p2.y; a3 = p3.x; d3 = p3.y;
            }
#pragma unroll
            for (int ni = 0; ni < 4; ni++) {
                int row = wn0 + ni * 8 + nf;
                const char* bp = stg + B_OFF + row * BROW + (kk + j2) * 4;
                float2 v01 = *(const float2*)bp;
                float2 v23 = *(const float2*)(bp + 32);   // k + 8
                float x0, x1, x2, x3;
                if (FUSE) {
                    x0 = fmaxf(fmaf(a0, v01.x, d0), 0.0f);
                    x1 = fmaxf(fmaf(a1, v01.y, d1), 0.0f);
                    x2 = fmaxf(fmaf(a2, v23.x, d2), 0.0f);
                    x3 = fmaxf(fmaf(a3, v23.y, d3), 0.0f);
                } else {
                    x0 = v01.x; x1 = v01.y; x2 = v23.x; x3 = v23.y;
                }
                uint32_t bfH[2], bfL[2];
                bfH[0] = pack_hi(x0, x1);
                bfH[1] = pack_hi(x2, x3);
                __nv_bfloat162 h0 = *(__nv_bfloat162*)&bfH[0];
                __nv_bfloat162 h1 = *(__nv_bfloat162*)&bfH[1];
                bfL[0] = pack_hi(x0 - __bfloat162float(h0.x), x1 - __bfloat162float(h0.y));
                bfL[1] = pack_hi(x2 - __bfloat162float(h1.x), x3 - __bfloat162float(h1.y));
#pragma unroll
                for (int mi = 0; mi < 4; mi++) {
                    mma16816(acc[mi * 4 + ni], afH[mi], bfH);
                    mma16816(acc[mi * 4 + ni], afH[mi], bfL);
                    mma16816(acc[mi * 4 + ni], afL[mi], bfH);
                }
            }
        }
    }
    __syncthreads();   // protect smem reuse

    // ---- epilogue: stage tile through SMEM, coalesced store + BN partials ----
    float* tile = (float*)smem;                    // [128][132] = 67584 B
    float* redS = (float*)(smem + 67584);          // [8][128]
    float* redQ = (float*)(smem + 71680);          // [8][128]

    const int o_thr = lane >> 2;
    const int n_thr = 2 * (lane & 3);
#pragma unroll
    for (int mi = 0; mi < 4; mi++) {
#pragma unroll
        for (int ni = 0; ni < 4; ni++) {
            int o0 = wm0 + mi * 16 + o_thr;
            int n0 = wn0 + ni * 8 + n_thr;
            float* d = acc[mi * 4 + ni];
            tile[n0 * 132 + o0]           = d[0];
            tile[(n0 + 1) * 132 + o0]     = d[1];
            tile[n0 * 132 + o0 + 8]       = d[2];
            tile[(n0 + 1) * 132 + o0 + 8] = d[3];
        }
    }
    __syncthreads();

    const int jrow = tid >> 5;
    const int o4   = (tid & 31) * 4;
    float s0 = 0, s1 = 0, s2 = 0, s3 = 0;
    float q0 = 0, q1 = 0, q2 = 0, q3 = 0;
#pragma unroll
    for (int i = 0; i < 16; i++) {
        int n = jrow + i * 8;
        float4 v = *(const float4*)&tile[n * 132 + o4];
        *(float4*)&Y[((size_t)b * Nq + nBase + n) * O + oBase + o4] = v;
        s0 += v.x; s1 += v.y; s2 += v.z; s3 += v.w;
        q0 += v.x * v.x; q1 += v.y * v.y; q2 += v.z * v.z; q3 += v.w * v.w;
    }
    *(float4*)&redS[jrow * 128 + o4] = make_float4(s0, s1, s2, s3);
    *(float4*)&redQ[jrow * 128 + o4] = make_float4(q0, q1, q2, q3);
    __syncthreads();

    if (tid < 128) {
        float S = 0, Q = 0;
#pragma unroll
        for (int j = 0; j < 8; j++) {
            S += redS[j * 128 + tid];
            Q += redQ[j * 128 + tid];
        }
        int slot = b * gridDim.x + blockIdx.x;
        g_psum[(size_t)(oBase + tid) * NSLOT + slot] = S;
        g_psq [(size_t)(oBase + tid) * NSLOT + slot] = Q;
    }
}

// ---------------- BN finalize: one block per channel -------------------------
__global__ void bn_fin(const float* __restrict__ g, const float* __restrict__ beta,
                       int layer) {
    int o = blockIdx.x;
    int t = threadIdx.x;   // 256
    float s = g_psum[(size_t)o * NSLOT + t] + g_psum[(size_t)o * NSLOT + t + 256];
    float q = g_psq [(size_t)o * NSLOT + t] + g_psq [(size_t)o * NSLOT + t + 256];
    __shared__ float ss[8], qq[8];
#pragma unroll
    for (int off = 16; off; off >>= 1) {
        s += __shfl_down_sync(0xffffffffu, s, off);
        q += __shfl_down_sync(0xffffffffu, q, off);
    }
    if ((t & 31) == 0) { ss[t >> 5] = s; qq[t >> 5] = q; }
    __syncthreads();
    if (t == 0) {
        float S = 0, Q = 0;
#pragma unroll
        for (int j = 0; j < 8; j++) { S += ss[j]; Q += qq[j]; }
        const float invP = 1.0f / (float)Pq;
        float mean = S * invP;
        float var  = Q * invP - mean * mean;
        float rstd = rsqrtf(var + 1e-5f);
        float a    = g[o] * rstd;
        g_affine[layer * 512 + o] = make_float2(a, beta[o] - mean * a);
    }
}

// ---------------- final BN+ReLU + transpose to [B,256,N] ---------------------
__global__ void final_out(const float* __restrict__ y, float* __restrict__ out) {
    __shared__ float t[32][33];
    int b = blockIdx.z, n0 = blockIdx.x * 32, c0 = blockIdx.y * 32;
    int tx = threadIdx.x, ty = threadIdx.y;
    const float* yb = y + (size_t)b * Nq * 256;
    float2 ad = g_affine[2 * 512 + c0 + tx];
#pragma unroll
    for (int i = 0; i < 4; i++) {
        int n = n0 + ty + 8 * i;
        float v = yb[(size_t)n * 256 + c0 + tx];
        t[ty + 8 * i][tx] = fmaxf(fmaf(ad.x, v, ad.y), 0.0f);
    }
    __syncthreads();
#pragma unroll
    for (int i = 0; i < 4; i++)
        out[((size_t)b * 256 + c0 + ty + 8 * i) * Nq + n0 + tx] = t[tx][ty + 8 * i];
}

// ---------------- launch -----------------------------------------------------
extern "C" void kernel_launch(void* const* d_in, const int* in_sizes, int n_in,
                              void* d_out, int out_size) {
    const float* xyz1    = (const float*)d_in[0];
    const float* xyz2    = (const float*)d_in[1];
    const float* points1 = (const float*)d_in[2];
    const float* points2 = (const float*)d_in[3];
    const float* w0  = (const float*)d_in[4];
    const float* g0  = (const float*)d_in[6];
    const float* be0 = (const float*)d_in[7];
    const float* w1  = (const float*)d_in[8];
    const float* g1  = (const float*)d_in[10];
    const float* be1 = (const float*)d_in[11];
    const float* w2  = (const float*)d_in[12];
    const float* g2  = (const float*)d_in[14];
    const float* be2 = (const float*)d_in[15];
    float* out = (float*)d_out;

    __nv_bfloat16 *Whi, *Wlo;
    float *bufA, *bufB;
    float2* affine;
    cudaGetSymbolAddress((void**)&Whi, g_Whi);
    cudaGetSymbolAddress((void**)&Wlo, g_Wlo);
    cudaGetSymbolAddress((void**)&bufA, g_bufA);
    cudaGetSymbolAddress((void**)&bufB, g_bufB);
    cudaGetSymbolAddress((void**)&affine, g_affine);

    cudaFuncSetAttribute(gemm_fused<false>, cudaFuncAttributeMaxDynamicSharedMemorySize, SMEM_TOT);
    cudaFuncSetAttribute(gemm_fused<true>,  cudaFuncAttributeMaxDynamicSharedMemorySize, SMEM_TOT);

    // weight splits
    wsplit<<<(512 * 512 + 255) / 256, 256>>>(w0, Whi,          Wlo,          512 * 512);
    wsplit<<<(512 * 512 + 255) / 256, 256>>>(w1, Whi + 262144, Wlo + 262144, 512 * 512);
    wsplit<<<(256 * 512 + 255) / 256, 256>>>(w2, Whi + 524288, Wlo + 524288, 256 * 512);

    // geometry + interpolation + concat (fp32 [B,N,512] into bufA)
    transpose_p2<<<dim3(Sq / 32, 256 / 32, Bq), dim3(32, 8)>>>(points2);
    knn3_kernel<<<dim3(Nq / 128, Bq), 128>>>(xyz1, xyz2);
    interp_concat<<<dim3(Nq / 32, Bq), 256>>>(points1);

    // layer 0: raw split (no affine)
    gemm_fused<false><<<dim3(Nq / NTt, 512 / MTt, Bq), 256, SMEM_TOT>>>(
        Whi, Wlo, bufA, bufB, nullptr, 512);
    bn_fin<<<512, 256>>>(g0, be0, 0);
    // layer 1: fused BN0+ReLU on bufB
    gemm_fused<true><<<dim3(Nq / NTt, 512 / MTt, Bq), 256, SMEM_TOT>>>(
        Whi + 262144, Wlo + 262144, bufB, bufA, affine, 512);
    bn_fin<<<512, 256>>>(g1, be1, 1);
    // layer 2: fused BN1+ReLU on bufA
    gemm_fused<true><<<dim3(Nq / NTt, 256 / MTt, Bq), 256, SMEM_TOT>>>(
        Whi + 524288, Wlo + 524288, bufA, bufB, affine + 512, 256);
    bn_fin<<<256, 256>>>(g2, be2, 2);
    final_out<<<dim3(Nq / 32, 8, Bq), dim3(32, 8)>>>(bufB, out);
}

// round 7
// speedup vs baseline: 1.2205x; 1.2205x over previous
#include <cuda_runtime.h>
#include <cuda_fp16.h>
#include <cstdint>
#include <math_constants.h>

#define Bq   8
#define Nq   8192
#define Sq   2048
#define Cin  512
#define NTt  128          // n-tile per CTA
#define MTt  128          // o-tile per CTA
#define KC   32           // k chunk
#define NCH  (Cin / KC)   // 16
#define NSLOT 512         // grid.x(64) * B(8)
#define Pq   (Bq * Nq)

// SMEM: 3 stages x [Ahi 8K | Alo 8K | B 8K] = 73728; epilogue overlays
// tile[128][132] (67584) + redS/redQ (8K) -> SMEM_TOT 75776.
#define STG      24576
#define SMEM_TOT 75776

// ---------------- scratch (device globals) ----------------------------------
__device__ __align__(16) __half g_Xh[(size_t)Bq * Nq * Cin];     // fp16 acts
__device__ __align__(16) float  g_Y [(size_t)Bq * Nq * Cin];     // fp32 raw out
__device__ __align__(16) __half g_Whi[655360];   // w0(256K) w1(256K) w2(128K)
__device__ __align__(16) __half g_Wlo[655360];
__device__ __align__(16) float g_p2t[(size_t)Bq * Sq * 256];
__device__ int   g_idx3[(size_t)Bq * Nq * 3];
__device__ float g_w3  [(size_t)Bq * Nq * 3];
__device__ float g_psum[512 * NSLOT];
__device__ float g_psq [512 * NSLOT];
__device__ __align__(16) float2 g_affine[3 * 512];   // (scale, shift)

// ---------------- helpers ----------------------------------------------------
__device__ __forceinline__ uint32_t smem_u32(const void* p) {
    uint32_t a;
    asm("{ .reg .u64 t; cvta.to.shared.u64 t, %1; cvt.u32.u64 %0, t; }"
        : "=r"(a) : "l"(p));
    return a;
}
#define SW64(off) ((off) ^ (((off) >> 3) & 0x30))
#define CP_ASYNC16(dst, src) \
    asm volatile("cp.async.cg.shared.global [%0], [%1], 16;" \
                 :: "r"(dst), "l"(src) : "memory")
#define CP_COMMIT()  asm volatile("cp.async.commit_group;" ::: "memory")
#define CP_WAIT(n)   asm volatile("cp.async.wait_group %0;" :: "n"(n) : "memory")

__device__ __forceinline__ void ldsm4(uint32_t* r, uint32_t addr) {
    asm volatile("ldmatrix.sync.aligned.m8n8.x4.shared.b16 {%0,%1,%2,%3}, [%4];"
                 : "=r"(r[0]), "=r"(r[1]), "=r"(r[2]), "=r"(r[3]) : "r"(addr));
}
__device__ __forceinline__ void ldsm2(uint32_t* r, uint32_t addr) {
    asm volatile("ldmatrix.sync.aligned.m8n8.x2.shared.b16 {%0,%1}, [%2];"
                 : "=r"(r[0]), "=r"(r[1]) : "r"(addr));
}
__device__ __forceinline__ void mma16816(float* d, const uint32_t* a, const uint32_t* b) {
    asm volatile("mma.sync.aligned.m16n8k16.row.col.f32.f16.f16.f32 "
                 "{%0,%1,%2,%3}, {%4,%5,%6,%7}, {%8,%9}, {%0,%1,%2,%3};"
                 : "+f"(d[0]), "+f"(d[1]), "+f"(d[2]), "+f"(d[3])
                 : "r"(a[0]), "r"(a[1]), "r"(a[2]), "r"(a[3]),
                   "r"(b[0]), "r"(b[1]));
}

// ---------------- transpose points2: [B,D2,S] -> [B,S,D2] -------------------
__global__ void transpose_p2(const float* __restrict__ p2) {
    __shared__ float t[32][33];
    int b  = blockIdx.z;
    int s0 = blockIdx.x * 32;
    int d0 = blockIdx.y * 32;
    int tx = threadIdx.x, ty = threadIdx.y;
    const float* src = p2 + (size_t)b * 256 * Sq;
    float*       dst = g_p2t + (size_t)b * Sq * 256;
#pragma unroll
    for (int i = 0; i < 4; i++)
        t[ty + i * 8][tx] = src[(size_t)(d0 + ty + i * 8) * Sq + s0 + tx];
    __syncthreads();
#pragma unroll
    for (int i = 0; i < 4; i++)
        dst[(size_t)(s0 + ty + i * 8) * 256 + d0 + tx] = t[tx][ty + i * 8];
}

// ---------------- 3-NN + inverse-distance weights ----------------------------
__global__ void knn3_kernel(const float* __restrict__ xyz1, const float* __restrict__ xyz2) {
    __shared__ float4 sp[Sq];
    int b   = blockIdx.y;
    int tid = threadIdx.x;
    const float* x2 = xyz2 + (size_t)b * 3 * Sq;
    for (int s = tid; s < Sq; s += 128) {
        float X = x2[s], Y = x2[Sq + s], Z = x2[2 * Sq + s];
        sp[s] = make_float4(X, Y, Z, X * X + Y * Y + Z * Z);
    }
    __syncthreads();
    int n = blockIdx.x * 128 + tid;
    const float* x1 = xyz1 + (size_t)b * 3 * Nq;
    float px = x1[n], py = x1[Nq + n], pz = x1[2 * Nq + n];
    float pn = px * px + py * py + pz * pz;
    float d1 = CUDART_INF_F, d2 = CUDART_INF_F, d3 = CUDART_INF_F;
    int   i1 = 0, i2 = 0, i3 = 0;
    for (int s = 0; s < Sq; s++) {
        float4 c = sp[s];
        float dot = px * c.x + py * c.y + pz * c.z;
        float d   = pn + c.w - 2.0f * dot;
        if (d < d3) {
            if (d < d2) {
                if (d < d1) { d3 = d2; i3 = i2; d2 = d1; i2 = i1; d1 = d; i1 = s; }
                else        { d3 = d2; i3 = i2; d2 = d;  i2 = s; }
            } else          { d3 = d;  i3 = s; }
        }
    }
    float r1 = 1.0f / (d1 + 1e-8f);
    float r2 = 1.0f / (d2 + 1e-8f);
    float r3 = 1.0f / (d3 + 1e-8f);
    float rs = r1 + r2 + r3;
    size_t base = ((size_t)b * Nq + n) * 3;
    g_idx3[base] = i1; g_idx3[base + 1] = i2; g_idx3[base + 2] = i3;
    g_w3[base] = r1 / rs; g_w3[base + 1] = r2 / rs; g_w3[base + 2] = r3 / rs;
}

// ---------------- interpolate + concat -> fp16 [B,N,512] ---------------------
__global__ void interp_concat(const float* __restrict__ p1) {
    __shared__ float t[32][33];
    int b   = blockIdx.y;
    int n0  = blockIdx.x * 32;
    int tid = threadIdx.x;
    int tx  = tid & 31, ty = tid >> 5;
    const float* p1b = p1 + (size_t)b * 256 * Nq;
    __half* xo = g_Xh + (size_t)b * Nq * Cin;

    for (int ct = 0; ct < 8; ct++) {
        int c0 = ct * 32;
#pragma unroll
        for (int i = 0; i < 4; i++)
            t[ty + 8 * i][tx] = p1b[(size_t)(c0 + ty + 8 * i) * Nq + n0 + tx];
        __syncthreads();
#pragma unroll
        for (int i = 0; i < 4; i++) {
            int n = n0 + ty + 8 * i;
            xo[(size_t)n * Cin + c0 + tx] = __float2half_rn(t[tx][ty + 8 * i]);
        }
        __syncthreads();
    }
    const float* p2tb = g_p2t + (size_t)b * Sq * 256;
    for (int nn = 0; nn < 32; nn++) {
        size_t base = ((size_t)b * Nq + n0 + nn) * 3;
        int   j0 = g_idx3[base], j1 = g_idx3[base + 1], j2 = g_idx3[base + 2];
        float w0 = g_w3[base], w1 = g_w3[base + 1], w2 = g_w3[base + 2];
        float v = w0 * p2tb[(size_t)j0 * 256 + tid]
                + w1 * p2tb[(size_t)j1 * 256 + tid]
                + w2 * p2tb[(size_t)j2 * 256 + tid];
        xo[(size_t)(n0 + nn) * Cin + 256 + tid] = __float2half_rn(v);
    }
}

// ---------------- weight fp32 -> fp16 hi/lo split ----------------------------
__global__ void wsplit(const float* __restrict__ w, __half* __restrict__ hi,
                       __half* __restrict__ lo, int n) {
    int i = blockIdx.x * 256 + threadIdx.x;
    if (i >= n) return;
    float v = w[i];
    __half h = __float2half_rn(v);
    hi[i] = h;
    lo[i] = __float2half_rn(v - __half2float(h));
}

// ---------------- fp16 2-stream GEMM + BN-stat epilogue ----------------------
// D[o,n] = sum_c (Whi+Wlo)[o,c] * X[n,c];  Y fp32 [B,N,O] + per-CTA partials.
__global__ __launch_bounds__(256, 2)
void gemm_mma(const __half* __restrict__ Whi, const __half* __restrict__ Wlo,
              const __half* __restrict__ Xh, float* __restrict__ Y, int O) {
    extern __shared__ char smem[];
    const int tid  = threadIdx.x;
    const int wid  = tid >> 5;
    const int lane = tid & 31;
    const int b     = blockIdx.z;
    const int nBase = blockIdx.x * NTt;
    const int oBase = blockIdx.y * MTt;
    const uint32_t sb = smem_u32(smem);
    const __half* Xb = Xh + (size_t)b * Nq * Cin;

    const int wm0 = (wid >> 2) * 64;
    const int wn0 = (wid & 3) * 32;

    float acc[16][4];
#pragma unroll
    for (int i = 0; i < 16; i++)
#pragma unroll
        for (int j = 0; j < 4; j++) acc[i][j] = 0.0f;

    auto load_chunk = [&](int kt, int s) {
        uint32_t st = sb + s * STG;
#pragma unroll
        for (int i = 0; i < 2; i++) {
            int idx = tid + i * 256;
            int row = idx >> 2, c = idx & 3;
            uint32_t sw = SW64((uint32_t)(row * 64 + c * 16));
            size_t gw = (size_t)(oBase + row) * Cin + kt + c * 8;
            CP_ASYNC16(st + sw,         Whi + gw);
            CP_ASYNC16(st + 8192 + sw,  Wlo + gw);
            CP_ASYNC16(st + 16384 + sw, Xb + (size_t)(nBase + row) * Cin + kt + c * 8);
        }
    };

    const int q  = lane >> 3, lr = lane & 7;
    const int a_row_off  = (q & 1) * 8 + lr;
    const int a_col_byte = (q >> 1) * 16;
    const int jj = lane & 15;
    const int b_row_off  = jj & 7;
    const int b_col_byte = (jj >> 3) * 16;

    load_chunk(0, 0);  CP_COMMIT();
    load_chunk(KC, 1); CP_COMMIT();

    for (int k = 0; k < NCH; k++) {
        if (k < NCH - 1) { CP_WAIT(1); } else { CP_WAIT(0); }
        __syncthreads();
        if (k + 2 < NCH) {
            load_chunk((k + 2) * KC, (k + 2) % 3);
            CP_COMMIT();
        }
        const int s = k % 3;
        uint32_t aHi = sb + s * STG;
        uint32_t aLo = aHi + 8192;
        uint32_t bAd = aHi + 16384;

#pragma unroll
        for (int kk = 0; kk < KC; kk += 16) {
            uint32_t afH[4][4], afL[4][4];
#pragma unroll
            for (int mi = 0; mi < 4; mi++) {
                int row = wm0 + mi * 16 + a_row_off;
                uint32_t sw = SW64((uint32_t)(row * 64 + kk * 2 + a_col_byte));
                ldsm4(afH[mi], aHi + sw);
                ldsm4(afL[mi], aLo + sw);
            }
#pragma unroll
            for (int ni = 0; ni < 4; ni++) {
                int row = wn0 + ni * 8 + b_row_off;
                uint32_t sw = SW64((uint32_t)(row * 64 + kk * 2 + b_col_byte));
                uint32_t bf[2];
                ldsm2(bf, bAd + sw);
#pragma unroll
                for (int mi = 0; mi < 4; mi++) {
                    mma16816(acc[mi * 4 + ni], afH[mi], bf);
                    mma16816(acc[mi * 4 + ni], afL[mi], bf);
                }
            }
        }
    }
    __syncthreads();   // protect smem reuse

    // ---- epilogue ----
    float* tile = (float*)smem;                    // [128][132]
    float* redS = (float*)(smem + 67584);          // [8][128]
    float* redQ = (float*)(smem + 71680);          // [8][128]

    const int o_thr = lane >> 2;
    const int n_thr = 2 * (lane & 3);
#pragma unroll
    for (int mi = 0; mi < 4; mi++) {
#pragma unroll
        for (int ni = 0; ni < 4; ni++) {
            int o0 = wm0 + mi * 16 + o_thr;
            int n0 = wn0 + ni * 8 + n_thr;
            float* d = acc[mi * 4 + ni];
            tile[n0 * 132 + o0]           = d[0];
            tile[(n0 + 1) * 132 + o0]     = d[1];
            tile[n0 * 132 + o0 + 8]       = d[2];
            tile[(n0 + 1) * 132 + o0 + 8] = d[3];
        }
    }
    __syncthreads();

    const int jrow = tid >> 5;
    const int o4   = (tid & 31) * 4;
    float s0 = 0, s1 = 0, s2 = 0, s3 = 0;
    float q0 = 0, q1 = 0, q2 = 0, q3 = 0;
#pragma unroll
    for (int i = 0; i < 16; i++) {
        int n = jrow + i * 8;
        float4 v = *(const float4*)&tile[n * 132 + o4];
        *(float4*)&Y[((size_t)b * Nq + nBase + n) * O + oBase + o4] = v;
        s0 += v.x; s1 += v.y; s2 += v.z; s3 += v.w;
        q0 += v.x * v.x; q1 += v.y * v.y; q2 += v.z * v.z; q3 += v.w * v.w;
    }
    *(float4*)&redS[jrow * 128 + o4] = make_float4(s0, s1, s2, s3);
    *(float4*)&redQ[jrow * 128 + o4] = make_float4(q0, q1, q2, q3);
    __syncthreads();

    if (tid < 128) {
        float S = 0, Q = 0;
#pragma unroll
        for (int j = 0; j < 8; j++) {
            S += redS[j * 128 + tid];
            Q += redQ[j * 128 + tid];
        }
        int slot = b * gridDim.x + blockIdx.x;
        g_psum[(size_t)(oBase + tid) * NSLOT + slot] = S;
        g_psq [(size_t)(oBase + tid) * NSLOT + slot] = Q;
    }
}

// ---------------- BN finalize: one block per channel -------------------------
__global__ void bn_fin(const float* __restrict__ g, const float* __restrict__ beta,
                       int layer) {
    int o = blockIdx.x;
    int t = threadIdx.x;   // 256
    float s = g_psum[(size_t)o * NSLOT + t] + g_psum[(size_t)o * NSLOT + t + 256];
    float q = g_psq [(size_t)o * NSLOT + t] + g_psq [(size_t)o * NSLOT + t + 256];
    __shared__ float ss[8], qq[8];
#pragma unroll
    for (int off = 16; off; off >>= 1) {
        s += __shfl_down_sync(0xffffffffu, s, off);
        q += __shfl_down_sync(0xffffffffu, q, off);
    }
    if ((t & 31) == 0) { ss[t >> 5] = s; qq[t >> 5] = q; }
    __syncthreads();
    if (t == 0) {
        float S = 0, Q = 0;
#pragma unroll
        for (int j = 0; j < 8; j++) { S += ss[j]; Q += qq[j]; }
        const float invP = 1.0f / (float)Pq;
        float mean = S * invP;
        float var  = Q * invP - mean * mean;
        float rstd = rsqrtf(var + 1e-5f);
        float a    = g[o] * rstd;
        g_affine[layer * 512 + o] = make_float2(a, beta[o] - mean * a);
    }
}

// ---------------- BN+ReLU + fp16 convert: Y [B,N,512] -> g_Xh ---------------
__global__ void act_convert(const float* __restrict__ y, const float2* __restrict__ aff) {
    size_t i4 = (size_t)blockIdx.x * 256 + threadIdx.x;
    float4 v = ((const float4*)y)[i4];
    int o = (int)((i4 * 4) & (Cin - 1));
    float2 p0 = aff[o], p1 = aff[o + 1], p2 = aff[o + 2], p3 = aff[o + 3];
    float x0 = fmaxf(fmaf(p0.x, v.x, p0.y), 0.0f);
    float x1 = fmaxf(fmaf(p1.x, v.y, p1.y), 0.0f);
    float x2 = fmaxf(fmaf(p2.x, v.z, p2.y), 0.0f);
    float x3 = fmaxf(fmaf(p3.x, v.w, p3.y), 0.0f);
    ((__half2*)g_Xh)[2 * i4]     = __floats2half2_rn(x0, x1);
    ((__half2*)g_Xh)[2 * i4 + 1] = __floats2half2_rn(x2, x3);
}

// ---------------- final BN+ReLU + transpose to [B,256,N] ---------------------
__global__ void final_out(const float* __restrict__ y, float* __restrict__ out) {
    __shared__ float t[32][33];
    int b = blockIdx.z, n0 = blockIdx.x * 32, c0 = blockIdx.y * 32;
    int tx = threadIdx.x, ty = threadIdx.y;
    const float* yb = y + (size_t)b * Nq * 256;
    float2 ad = g_affine[2 * 512 + c0 + tx];
#pragma unroll
    for (int i = 0; i < 4; i++) {
        int n = n0 + ty + 8 * i;
        float v = yb[(size_t)n * 256 + c0 + tx];
        t[ty + 8 * i][tx] = fmaxf(fmaf(ad.x, v, ad.y), 0.0f);
    }
    __syncthreads();
#pragma unroll
    for (int i = 0; i < 4; i++)
        out[((size_t)b * 256 + c0 + ty + 8 * i) * Nq + n0 + tx] = t[tx][ty + 8 * i];
}

// ---------------- launch -----------------------------------------------------
extern "C" void kernel_launch(void* const* d_in, const int* in_sizes, int n_in,
                              void* d_out, int out_size) {
    const float* xyz1    = (const float*)d_in[0];
    const float* xyz2    = (const float*)d_in[1];
    const float* points1 = (const float*)d_in[2];
    const float* points2 = (const float*)d_in[3];
    const float* w0  = (const float*)d_in[4];
    const float* g0  = (const float*)d_in[6];
    const float* be0 = (const float*)d_in[7];
    const float* w1  = (const float*)d_in[8];
    const float* g1  = (const float*)d_in[10];
    const float* be1 = (const float*)d_in[11];
    const float* w2  = (const float*)d_in[12];
    const float* g2  = (const float*)d_in[14];
    const float* be2 = (const float*)d_in[15];
    float* out = (float*)d_out;

    __half *Whi, *Wlo, *Xh;
    float *Y;
    float2* affine;
    cudaGetSymbolAddress((void**)&Whi, g_Whi);
    cudaGetSymbolAddress((void**)&Wlo, g_Wlo);
    cudaGetSymbolAddress((void**)&Xh, g_Xh);
    cudaGetSymbolAddress((void**)&Y, g_Y);
    cudaGetSymbolAddress((void**)&affine, g_affine);
    (void)Xh;

    cudaFuncSetAttribute(gemm_mma, cudaFuncAttributeMaxDynamicSharedMemorySize, SMEM_TOT);

    // weight splits
    wsplit<<<(512 * 512 + 255) / 256, 256>>>(w0, Whi,          Wlo,          512 * 512);
    wsplit<<<(512 * 512 + 255) / 256, 256>>>(w1, Whi + 262144, Wlo + 262144, 512 * 512);
    wsplit<<<(256 * 512 + 255) / 256, 256>>>(w2, Whi + 524288, Wlo + 524288, 256 * 512);

    // geometry + interpolation + concat (fp16 [B,N,512] into g_Xh)
    transpose_p2<<<dim3(Sq / 32, 256 / 32, Bq), dim3(32, 8)>>>(points2);
    knn3_kernel<<<dim3(Nq / 128, Bq), 128>>>(xyz1, xyz2);
    interp_concat<<<dim3(Nq / 32, Bq), 256>>>(points1);

    // layer 0
    gemm_mma<<<dim3(Nq / NTt, 512 / MTt, Bq), 256, SMEM_TOT>>>(Whi, Wlo, Xh, Y, 512);
    bn_fin<<<512, 256>>>(g0, be0, 0);
    act_convert<<<(Bq * Nq * Cin / 4) / 256, 256>>>(Y, affine);
    // layer 1
    gemm_mma<<<dim3(Nq / NTt, 512 / MTt, Bq), 256, SMEM_TOT>>>(Whi + 262144, Wlo + 262144, Xh, Y, 512);
    bn_fin<<<512, 256>>>(g1, be1, 1);
    act_convert<<<(Bq * Nq * Cin / 4) / 256, 256>>>(Y, affine + 512);
    // layer 2
    gemm_mma<<<dim3(Nq / NTt, 256 / MTt, Bq), 256, SMEM_TOT>>>(Whi + 524288, Wlo + 524288, Xh, Y, 256);
    bn_fin<<<256, 256>>>(g2, be2, 2);
    final_out<<<dim3(Nq / 32, 8, Bq), dim3(32, 8)>>>(Y, out);
}

// round 8
// speedup vs baseline: 1.2552x; 1.0285x over previous
#include <cuda_runtime.h>
#include <cuda_fp16.h>
#include <cstdint>
#include <math_constants.h>

#define Bq   8
#define Nq   8192
#define Sq   2048
#define Cin  512
#define NTt  256          // n-tile per CTA
#define MTt  128          // o-tile per CTA
#define KC   32           // k chunk
#define NCH  (Cin / KC)   // 16
#define NSLOT 256         // grid.x(32) * B(8)
#define Pq   (Bq * Nq)

// SMEM: 3 stages x [Ahi 8K | Alo 8K | B 16K] = 98304.
// Epilogue overlays: tile[256][68] f32 (69632) + redS/redQ (16K) = 86016.
#define STG      32768
#define B_OFF    16384
#define SMEM_TOT 98304

// ---------------- scratch (device globals) ----------------------------------
__device__ __align__(16) __half g_Xh[(size_t)Bq * Nq * Cin];     // fp16 acts
__device__ __align__(16) float  g_Y [(size_t)Bq * Nq * Cin];     // fp32 raw out
__device__ __align__(16) __half g_Whi[655360];   // w0(256K) w1(256K) w2(128K)
__device__ __align__(16) __half g_Wlo[655360];
__device__ __align__(16) float g_p2t[(size_t)Bq * Sq * 256];
__device__ int   g_idx3[(size_t)Bq * Nq * 3];
__device__ float g_w3  [(size_t)Bq * Nq * 3];
__device__ float g_psum[512 * NSLOT];
__device__ float g_psq [512 * NSLOT];
__device__ __align__(16) float2 g_affine[3 * 512];   // (scale, shift)

// ---------------- helpers ----------------------------------------------------
__device__ __forceinline__ uint32_t smem_u32(const void* p) {
    uint32_t a;
    asm("{ .reg .u64 t; cvta.to.shared.u64 t, %1; cvt.u32.u64 %0, t; }"
        : "=r"(a) : "l"(p));
    return a;
}
#define SW64(off) ((off) ^ (((off) >> 3) & 0x30))
#define CP_ASYNC16(dst, src) \
    asm volatile("cp.async.cg.shared.global [%0], [%1], 16;" \
                 :: "r"(dst), "l"(src) : "memory")
#define CP_COMMIT()  asm volatile("cp.async.commit_group;" ::: "memory")
#define CP_WAIT(n)   asm volatile("cp.async.wait_group %0;" :: "n"(n) : "memory")

__device__ __forceinline__ void ldsm4(uint32_t* r, uint32_t addr) {
    asm volatile("ldmatrix.sync.aligned.m8n8.x4.shared.b16 {%0,%1,%2,%3}, [%4];"
                 : "=r"(r[0]), "=r"(r[1]), "=r"(r[2]), "=r"(r[3]) : "r"(addr));
}
__device__ __forceinline__ void mma16816(float* d, const uint32_t* a, const uint32_t* b) {
    asm volatile("mma.sync.aligned.m16n8k16.row.col.f32.f16.f16.f32 "
                 "{%0,%1,%2,%3}, {%4,%5,%6,%7}, {%8,%9}, {%0,%1,%2,%3};"
                 : "+f"(d[0]), "+f"(d[1]), "+f"(d[2]), "+f"(d[3])
                 : "r"(a[0]), "r"(a[1]), "r"(a[2]), "r"(a[3]),
                   "r"(b[0]), "r"(b[1]));
}

// ---------------- transpose points2: [B,D2,S] -> [B,S,D2] -------------------
__global__ void transpose_p2(const float* __restrict__ p2) {
    __shared__ float t[32][33];
    int b  = blockIdx.z;
    int s0 = blockIdx.x * 32;
    int d0 = blockIdx.y * 32;
    int tx = threadIdx.x, ty = threadIdx.y;
    const float* src = p2 + (size_t)b * 256 * Sq;
    float*       dst = g_p2t + (size_t)b * Sq * 256;
#pragma unroll
    for (int i = 0; i < 4; i++)
        t[ty + i * 8][tx] = src[(size_t)(d0 + ty + i * 8) * Sq + s0 + tx];
    __syncthreads();
#pragma unroll
    for (int i = 0; i < 4; i++)
        dst[(size_t)(s0 + ty + i * 8) * 256 + d0 + tx] = t[tx][ty + i * 8];
}

// ---------------- 3-NN + inverse-distance weights ----------------------------
__global__ void knn3_kernel(const float* __restrict__ xyz1, const float* __restrict__ xyz2) {
    __shared__ float4 sp[Sq];
    int b   = blockIdx.y;
    int tid = threadIdx.x;
    const float* x2 = xyz2 + (size_t)b * 3 * Sq;
    for (int s = tid; s < Sq; s += 128) {
        float X = x2[s], Y = x2[Sq + s], Z = x2[2 * Sq + s];
        sp[s] = make_float4(X, Y, Z, X * X + Y * Y + Z * Z);
    }
    __syncthreads();
    int n = blockIdx.x * 128 + tid;
    const float* x1 = xyz1 + (size_t)b * 3 * Nq;
    float px = x1[n], py = x1[Nq + n], pz = x1[2 * Nq + n];
    float pn = px * px + py * py + pz * pz;
    float d1 = CUDART_INF_F, d2 = CUDART_INF_F, d3 = CUDART_INF_F;
    int   i1 = 0, i2 = 0, i3 = 0;
    for (int s = 0; s < Sq; s++) {
        float4 c = sp[s];
        float dot = px * c.x + py * c.y + pz * c.z;
        float d   = pn + c.w - 2.0f * dot;
        if (d < d3) {
            if (d < d2) {
                if (d < d1) { d3 = d2; i3 = i2; d2 = d1; i2 = i1; d1 = d; i1 = s; }
                else        { d3 = d2; i3 = i2; d2 = d;  i2 = s; }
            } else          { d3 = d;  i3 = s; }
        }
    }
    float r1 = 1.0f / (d1 + 1e-8f);
    float r2 = 1.0f / (d2 + 1e-8f);
    float r3 = 1.0f / (d3 + 1e-8f);
    float rs = r1 + r2 + r3;
    size_t base = ((size_t)b * Nq + n) * 3;
    g_idx3[base] = i1; g_idx3[base + 1] = i2; g_idx3[base + 2] = i3;
    g_w3[base] = r1 / rs; g_w3[base + 1] = r2 / rs; g_w3[base + 2] = r3 / rs;
}

// ---------------- interpolate + concat -> fp16 [B,N,512] ---------------------
__global__ void interp_concat(const float* __restrict__ p1) {
    __shared__ float t[32][33];
    int b   = blockIdx.y;
    int n0  = blockIdx.x * 32;
    int tid = threadIdx.x;
    int tx  = tid & 31, ty = tid >> 5;
    const float* p1b = p1 + (size_t)b * 256 * Nq;
    __half* xo = g_Xh + (size_t)b * Nq * Cin;

    for (int ct = 0; ct < 8; ct++) {
        int c0 = ct * 32;
#pragma unroll
        for (int i = 0; i < 4; i++)
            t[ty + 8 * i][tx] = p1b[(size_t)(c0 + ty + 8 * i) * Nq + n0 + tx];
        __syncthreads();
#pragma unroll
        for (int i = 0; i < 4; i++) {
            int n = n0 + ty + 8 * i;
            xo[(size_t)n * Cin + c0 + tx] = __float2half_rn(t[tx][ty + 8 * i]);
        }
        __syncthreads();
    }
    const float* p2tb = g_p2t + (size_t)b * Sq * 256;
    for (int nn = 0; nn < 32; nn++) {
        size_t base = ((size_t)b * Nq + n0 + nn) * 3;
        int   j0 = g_idx3[base], j1 = g_idx3[base + 1], j2 = g_idx3[base + 2];
        float w0 = g_w3[base], w1 = g_w3[base + 1], w2 = g_w3[base + 2];
        float v = w0 * p2tb[(size_t)j0 * 256 + tid]
                + w1 * p2tb[(size_t)j1 * 256 + tid]
                + w2 * p2tb[(size_t)j2 * 256 + tid];
        xo[(size_t)(n0 + nn) * Cin + 256 + tid] = __float2half_rn(v);
    }
}

// ---------------- weight fp32 -> fp16 hi/lo split ----------------------------
__global__ void wsplit(const float* __restrict__ w, __half* __restrict__ hi,
                       __half* __restrict__ lo, int n) {
    int i = blockIdx.x * 256 + threadIdx.x;
    if (i >= n) return;
    float v = w[i];
    __half h = __float2half_rn(v);
    hi[i] = h;
    lo[i] = __float2half_rn(v - __half2float(h));
}

// ---------------- fp16 2-stream GEMM, 128x256 CTA / 64x64 warptile -----------
// D[o,n] = sum_c (Whi+Wlo)[o,c] * X[n,c];  Y fp32 [B,N,O] + per-CTA partials.
__global__ __launch_bounds__(256, 1)
void gemm_mma(const __half* __restrict__ Whi, const __half* __restrict__ Wlo,
              const __half* __restrict__ Xh, float* __restrict__ Y, int O) {
    extern __shared__ char smem[];
    const int tid  = threadIdx.x;
    const int wid  = tid >> 5;
    const int lane = tid & 31;
    const int b     = blockIdx.z;
    const int nBase = blockIdx.x * NTt;
    const int oBase = blockIdx.y * MTt;
    const uint32_t sb = smem_u32(smem);
    const __half* Xb = Xh + (size_t)b * Nq * Cin;

    const int wm0 = (wid & 1) * 64;     // o
    const int wn0 = (wid >> 1) * 64;    // n

    float acc[32][4];                   // [mi*8 + ni][4]
#pragma unroll
    for (int i = 0; i < 32; i++)
#pragma unroll
        for (int j = 0; j < 4; j++) acc[i][j] = 0.0f;

    auto load_chunk = [&](int kt, int s) {
        uint32_t st = sb + s * STG;
#pragma unroll
        for (int i = 0; i < 2; i++) {   // A hi + lo: 128 rows x 64B
            int idx = tid + i * 256;
            int row = idx >> 2, c = idx & 3;
            uint32_t sw = SW64((uint32_t)(row * 64 + c * 16));
            size_t gw = (size_t)(oBase + row) * Cin + kt + c * 8;
            CP_ASYNC16(st + sw,        Whi + gw);
            CP_ASYNC16(st + 8192 + sw, Wlo + gw);
        }
#pragma unroll
        for (int i = 0; i < 4; i++) {   // B: 256 rows x 64B
            int idx = tid + i * 256;
            int row = idx >> 2, c = idx & 3;
            uint32_t sw = SW64((uint32_t)(row * 64 + c * 16));
            CP_ASYNC16(st + B_OFF + sw,
                       Xb + (size_t)(nBase + row) * Cin + kt + c * 8);
        }
    };

    const int q  = lane >> 3, lr = lane & 7;
    const int a_row_off  = (q & 1) * 8 + lr;   // A x4: t0(k lo) t1(k hi) per m16
    const int a_col_byte = (q >> 1) * 16;
    const int b_row_off  = (q >> 1) * 8 + lr;  // B x4: t0/t1 = n tile, t2/t3 = n+8
    const int b_col_byte = (q & 1) * 16;

    load_chunk(0, 0);  CP_COMMIT();
    load_chunk(KC, 1); CP_COMMIT();

    for (int k = 0; k < NCH; k++) {
        if (k < NCH - 1) { CP_WAIT(1); } else { CP_WAIT(0); }
        __syncthreads();
        if (k + 2 < NCH) {
            load_chunk((k + 2) * KC, (k + 2) % 3);
            CP_COMMIT();
        }
        const int s = k % 3;
        uint32_t aHi = sb + s * STG;
        uint32_t aLo = aHi + 8192;
        uint32_t bAd = aHi + B_OFF;

#pragma unroll
        for (int kk = 0; kk < KC; kk += 16) {
            uint32_t afH[4][4], afL[4][4];
#pragma unroll
            for (int mi = 0; mi < 4; mi++) {
                int row = wm0 + mi * 16 + a_row_off;
                uint32_t sw = SW64((uint32_t)(row * 64 + kk * 2 + a_col_byte));
                ldsm4(afH[mi], aHi + sw);
                ldsm4(afL[mi], aLo + sw);
            }
#pragma unroll
            for (int nj = 0; nj < 4; nj++) {         // n-tile pair (2nj, 2nj+1)
                int row = wn0 + nj * 16 + b_row_off;
                uint32_t sw = SW64((uint32_t)(row * 64 + kk * 2 + b_col_byte));
                uint32_t bf[4];                       // r0,r1: n tile; r2,r3: n+8
                ldsm4(bf, bAd + sw);
#pragma unroll
                for (int mi = 0; mi < 4; mi++) {
                    mma16816(acc[mi * 8 + 2 * nj],     afH[mi], bf);
                    mma16816(acc[mi * 8 + 2 * nj],     afL[mi], bf);
                    mma16816(acc[mi * 8 + 2 * nj + 1], afH[mi], bf + 2);
                    mma16816(acc[mi * 8 + 2 * nj + 1], afL[mi], bf + 2);
                }
            }
        }
    }

    // ---- epilogue: two o-half passes through smem tile [256 n][68 o] --------
    float* tile = (float*)smem;                     // 256*68*4 = 69632 B
    float* redS = (float*)(smem + 69632);           // [16][128]
    float* redQ = (float*)(smem + 69632 + 8192);    // [16][128]

    const int o_thr = lane >> 2;
    const int n_thr = 2 * (lane & 3);
    const int nrow0 = tid >> 4;          // 0..15
    const int o4    = (tid & 15) * 4;    // 0..60
    float sS[2][4] = {}, sQ[2][4] = {};

#pragma unroll
    for (int p = 0; p < 2; p++) {
        __syncthreads();
        if ((wid & 1) == p) {
#pragma unroll
            for (int mi = 0; mi < 4; mi++) {
#pragma unroll
                for (int ni = 0; ni < 8; ni++) {
                    int o0 = mi * 16 + o_thr;
                    int n0 = wn0 + ni * 8 + n_thr;
                    float* d = acc[mi * 8 + ni];
                    tile[n0 * 68 + o0]           = d[0];
                    tile[(n0 + 1) * 68 + o0]     = d[1];
                    tile[n0 * 68 + o0 + 8]       = d[2];
                    tile[(n0 + 1) * 68 + o0 + 8] = d[3];
                }
            }
        }
        __syncthreads();
#pragma unroll
        for (int i = 0; i < 16; i++) {
            int n = nrow0 + 16 * i;
            float4 v = *(const float4*)&tile[n * 68 + o4];
            *(float4*)&Y[((size_t)b * Nq + nBase + n) * O + oBase + 64 * p + o4] = v;
            sS[p][0] += v.x; sS[p][1] += v.y; sS[p][2] += v.z; sS[p][3] += v.w;
            sQ[p][0] += v.x * v.x; sQ[p][1] += v.y * v.y;
            sQ[p][2] += v.z * v.z; sQ[p][3] += v.w * v.w;
        }
        *(float4*)&redS[nrow0 * 128 + 64 * p + o4] =
            make_float4(sS[p][0], sS[p][1], sS[p][2], sS[p][3]);
        *(float4*)&redQ[nrow0 * 128 + 64 * p + o4] =
            make_float4(sQ[p][0], sQ[p][1], sQ[p][2], sQ[p][3]);
    }
    __syncthreads();

    if (tid < 128) {
        float S = 0, Q = 0;
#pragma unroll
        for (int j = 0; j < 16; j++) {
            S += redS[j * 128 + tid];
            Q += redQ[j * 128 + tid];
        }
        int slot = b * gridDim.x + blockIdx.x;
        g_psum[(size_t)(oBase + tid) * NSLOT + slot] = S;
        g_psq [(size_t)(oBase + tid) * NSLOT + slot] = Q;
    }
}

// ---------------- BN finalize: one block per channel -------------------------
__global__ void bn_fin(const float* __restrict__ g, const float* __restrict__ beta,
                       int layer) {
    int o = blockIdx.x;
    int t = threadIdx.x;   // 256
    float s = g_psum[(size_t)o * NSLOT + t];
    float q = g_psq [(size_t)o * NSLOT + t];
    __shared__ float ss[8], qq[8];
#pragma unroll
    for (int off = 16; off; off >>= 1) {
        s += __shfl_down_sync(0xffffffffu, s, off);
        q += __shfl_down_sync(0xffffffffu, q, off);
    }
    if ((t & 31) == 0) { ss[t >> 5] = s; qq[t >> 5] = q; }
    __syncthreads();
    if (t == 0) {
        float S = 0, Q = 0;
#pragma unroll
        for (int j = 0; j < 8; j++) { S += ss[j]; Q += qq[j]; }
        const float invP = 1.0f / (float)Pq;
        float mean = S * invP;
        float var  = Q * invP - mean * mean;
        float rstd = rsqrtf(var + 1e-5f);
        float a    = g[o] * rstd;
        g_affine[layer * 512 + o] = make_float2(a, beta[o] - mean * a);
    }
}

// ---------------- BN+ReLU + fp16 convert: Y [B,N,512] -> g_Xh ---------------
__global__ void act_convert(const float* __restrict__ y, const float2* __restrict__ aff) {
    size_t i4 = (size_t)blockIdx.x * 256 + threadIdx.x;
    float4 v = ((const float4*)y)[i4];
    int o = (int)((i4 * 4) & (Cin - 1));
    float2 p0 = aff[o], p1 = aff[o + 1], p2 = aff[o + 2], p3 = aff[o + 3];
    float x0 = fmaxf(fmaf(p0.x, v.x, p0.y), 0.0f);
    float x1 = fmaxf(fmaf(p1.x, v.y, p1.y), 0.0f);
    float x2 = fmaxf(fmaf(p2.x, v.z, p2.y), 0.0f);
    float x3 = fmaxf(fmaf(p3.x, v.w, p3.y), 0.0f);
    ((__half2*)g_Xh)[2 * i4]     = __floats2half2_rn(x0, x1);
    ((__half2*)g_Xh)[2 * i4 + 1] = __floats2half2_rn(x2, x3);
}

// ---------------- final BN+ReLU + transpose to [B,256,N] ---------------------
__global__ void final_out(const float* __restrict__ y, float* __restrict__ out) {
    __shared__ float t[32][33];
    int b = blockIdx.z, n0 = blockIdx.x * 32, c0 = blockIdx.y * 32;
    int tx = threadIdx.x, ty = threadIdx.y;
    const float* yb = y + (size_t)b * Nq * 256;
    float2 ad = g_affine[2 * 512 + c0 + tx];
#pragma unroll
    for (int i = 0; i < 4; i++) {
        int n = n0 + ty + 8 * i;
        float v = yb[(size_t)n * 256 + c0 + tx];
        t[ty + 8 * i][tx] = fmaxf(fmaf(ad.x, v, ad.y), 0.0f);
    }
    __syncthreads();
#pragma unroll
    for (int i = 0; i < 4; i++)
        out[((size_t)b * 256 + c0 + ty + 8 * i) * Nq + n0 + tx] = t[tx][ty + 8 * i];
}

// ---------------- launch -----------------------------------------------------
extern "C" void kernel_launch(void* const* d_in, const int* in_sizes, int n_in,
                              void* d_out, int out_size) {
    const float* xyz1    = (const float*)d_in[0];
    const float* xyz2    = (const float*)d_in[1];
    const float* points1 = (const float*)d_in[2];
    const float* points2 = (const float*)d_in[3];
    const float* w0  = (const float*)d_in[4];
    const float* g0  = (const float*)d_in[6];
    const float* be0 = (const float*)d_in[7];
    const float* w1  = (const float*)d_in[8];
    const float* g1  = (const float*)d_in[10];
    const float* be1 = (const float*)d_in[11];
    const float* w2  = (const float*)d_in[12];
    const float* g2  = (const float*)d_in[14];
    const float* be2 = (const float*)d_in[15];
    float* out = (float*)d_out;

    __half *Whi, *Wlo, *Xh;
    float *Y;
    float2* affine;
    cudaGetSymbolAddress((void**)&Whi, g_Whi);
    cudaGetSymbolAddress((void**)&Wlo, g_Wlo);
    cudaGetSymbolAddress((void**)&Xh, g_Xh);
    cudaGetSymbolAddress((void**)&Y, g_Y);
    cudaGetSymbolAddress((void**)&affine, g_affine);

    cudaFuncSetAttribute(gemm_mma, cudaFuncAttributeMaxDynamicSharedMemorySize, SMEM_TOT);

    // weight splits
    wsplit<<<(512 * 512 + 255) / 256, 256>>>(w0, Whi,          Wlo,          512 * 512);
    wsplit<<<(512 * 512 + 255) / 256, 256>>>(w1, Whi + 262144, Wlo + 262144, 512 * 512);
    wsplit<<<(256 * 512 + 255) / 256, 256>>>(w2, Whi + 524288, Wlo + 524288, 256 * 512);

    // geometry + interpolation + concat (fp16 [B,N,512] into g_Xh)
    transpose_p2<<<dim3(Sq / 32, 256 / 32, Bq), dim3(32, 8)>>>(points2);
    knn3_kernel<<<dim3(Nq / 128, Bq), 128>>>(xyz1, xyz2);
    interp_concat<<<dim3(Nq / 32, Bq), 256>>>(points1);

    // layer 0
    gemm_mma<<<dim3(Nq / NTt, 512 / MTt, Bq), 256, SMEM_TOT>>>(Whi, Wlo, Xh, Y, 512);
    bn_fin<<<512, 256>>>(g0, be0, 0);
    act_convert<<<(Bq * Nq * Cin / 4) / 256, 256>>>(Y, affine);
    // layer 1
    gemm_mma<<<dim3(Nq / NTt, 512 / MTt, Bq), 256, SMEM_TOT>>>(Whi + 262144, Wlo + 262144, Xh, Y, 512);
    bn_fin<<<512, 256>>>(g1, be1, 1);
    act_convert<<<(Bq * Nq * Cin / 4) / 256, 256>>>(Y, affine + 512);
    // layer 2
    gemm_mma<<<dim3(Nq / NTt, 256 / MTt, Bq), 256, SMEM_TOT>>>(Whi + 524288, Wlo + 524288, Xh, Y, 256);
    bn_fin<<<256, 256>>>(g2, be2, 2);
    final_out<<<dim3(Nq / 32, 8, Bq), dim3(32, 8)>>>(Y, out);
}

// round 9
// speedup vs baseline: 1.5791x; 1.2580x over previous
#include <cuda_runtime.h>
#include <cuda_fp16.h>
#include <cstdint>
#include <math_constants.h>

#define Bq   8
#define Nq   8192
#define Sq   2048
#define Cin  512
#define NTt  256          // n-tile per CTA
#define MTt  128          // o-tile per CTA
#define KC   32           // k chunk
#define NCH  (Cin / KC)   // 16
#define NSLOT 256         // grid.x(32) * B(8)
#define Pq   (Bq * Nq)

// SMEM: 3 stages x [A 8K | B 16K] = 73728.
// Epilogue overlays: tile[256][68] f32 (69632) + redS/redQ (16K) = 86016.
#define STG      24576
#define B_OFF    8192
#define SMEM_TOT 86016

// ---------------- scratch (device globals) ----------------------------------
__device__ __align__(16) __half g_Xh[(size_t)Bq * Nq * Cin];     // fp16 acts
__device__ __align__(16) float  g_Y [(size_t)Bq * Nq * Cin];     // fp32 raw out
__device__ __align__(16) __half g_Wh[655360];    // w0(256K) w1(256K) w2(128K)
__device__ __align__(16) float g_p2t[(size_t)Bq * Sq * 256];
__device__ int   g_idx3[(size_t)Bq * Nq * 3];
__device__ float g_w3  [(size_t)Bq * Nq * 3];
__device__ float g_psum[512 * NSLOT];
__device__ float g_psq [512 * NSLOT];
__device__ __align__(16) float2 g_affine[3 * 512];   // (scale, shift)

// ---------------- helpers ----------------------------------------------------
__device__ __forceinline__ uint32_t smem_u32(const void* p) {
    uint32_t a;
    asm("{ .reg .u64 t; cvta.to.shared.u64 t, %1; cvt.u32.u64 %0, t; }"
        : "=r"(a) : "l"(p));
    return a;
}
#define SW64(off) ((off) ^ (((off) >> 3) & 0x30))
#define CP_ASYNC16(dst, src) \
    asm volatile("cp.async.cg.shared.global [%0], [%1], 16;" \
                 :: "r"(dst), "l"(src) : "memory")
#define CP_COMMIT()  asm volatile("cp.async.commit_group;" ::: "memory")
#define CP_WAIT(n)   asm volatile("cp.async.wait_group %0;" :: "n"(n) : "memory")

__device__ __forceinline__ void ldsm4(uint32_t* r, uint32_t addr) {
    asm volatile("ldmatrix.sync.aligned.m8n8.x4.shared.b16 {%0,%1,%2,%3}, [%4];"
                 : "=r"(r[0]), "=r"(r[1]), "=r"(r[2]), "=r"(r[3]) : "r"(addr));
}
__device__ __forceinline__ void mma16816(float* d, const uint32_t* a, const uint32_t* b) {
    asm volatile("mma.sync.aligned.m16n8k16.row.col.f32.f16.f16.f32 "
                 "{%0,%1,%2,%3}, {%4,%5,%6,%7}, {%8,%9}, {%0,%1,%2,%3};"
                 : "+f"(d[0]), "+f"(d[1]), "+f"(d[2]), "+f"(d[3])
                 : "r"(a[0]), "r"(a[1]), "r"(a[2]), "r"(a[3]),
                   "r"(b[0]), "r"(b[1]));
}

// ---------------- transpose points2: [B,D2,S] -> [B,S,D2] -------------------
__global__ void transpose_p2(const float* __restrict__ p2) {
    __shared__ float t[32][33];
    int b  = blockIdx.z;
    int s0 = blockIdx.x * 32;
    int d0 = blockIdx.y * 32;
    int tx = threadIdx.x, ty = threadIdx.y;
    const float* src = p2 + (size_t)b * 256 * Sq;
    float*       dst = g_p2t + (size_t)b * Sq * 256;
#pragma unroll
    for (int i = 0; i < 4; i++)
        t[ty + i * 8][tx] = src[(size_t)(d0 + ty + i * 8) * Sq + s0 + tx];
    __syncthreads();
#pragma unroll
    for (int i = 0; i < 4; i++)
        dst[(size_t)(s0 + ty + i * 8) * 256 + d0 + tx] = t[tx][ty + i * 8];
}

// ---------------- 3-NN + inverse-distance weights ----------------------------
__global__ void knn3_kernel(const float* __restrict__ xyz1, const float* __restrict__ xyz2) {
    __shared__ float4 sp[Sq];
    int b   = blockIdx.y;
    int tid = threadIdx.x;
    const float* x2 = xyz2 + (size_t)b * 3 * Sq;
    for (int s = tid; s < Sq; s += 128) {
        float X = x2[s], Y = x2[Sq + s], Z = x2[2 * Sq + s];
        sp[s] = make_float4(X, Y, Z, X * X + Y * Y + Z * Z);
    }
    __syncthreads();
    int n = blockIdx.x * 128 + tid;
    const float* x1 = xyz1 + (size_t)b * 3 * Nq;
    float px = x1[n], py = x1[Nq + n], pz = x1[2 * Nq + n];
    float pn = px * px + py * py + pz * pz;
    float d1 = CUDART_INF_F, d2 = CUDART_INF_F, d3 = CUDART_INF_F;
    int   i1 = 0, i2 = 0, i3 = 0;
    for (int s = 0; s < Sq; s++) {
        float4 c = sp[s];
        float dot = px * c.x + py * c.y + pz * c.z;
        float d   = pn + c.w - 2.0f * dot;
        if (d < d3) {
            if (d < d2) {
                if (d < d1) { d3 = d2; i3 = i2; d2 = d1; i2 = i1; d1 = d; i1 = s; }
                else        { d3 = d2; i3 = i2; d2 = d;  i2 = s; }
            } else          { d3 = d;  i3 = s; }
        }
    }
    float r1 = 1.0f / (d1 + 1e-8f);
    float r2 = 1.0f / (d2 + 1e-8f);
    float r3 = 1.0f / (d3 + 1e-8f);
    float rs = r1 + r2 + r3;
    size_t base = ((size_t)b * Nq + n) * 3;
    g_idx3[base] = i1; g_idx3[base + 1] = i2; g_idx3[base + 2] = i3;
    g_w3[base] = r1 / rs; g_w3[base + 1] = r2 / rs; g_w3[base + 2] = r3 / rs;
}

// ---------------- interpolate + concat -> fp16 [B,N,512] ---------------------
__global__ void interp_concat(const float* __restrict__ p1) {
    __shared__ float t[32][33];
    int b   = blockIdx.y;
    int n0  = blockIdx.x * 32;
    int tid = threadIdx.x;
    int tx  = tid & 31, ty = tid >> 5;
    const float* p1b = p1 + (size_t)b * 256 * Nq;
    __half* xo = g_Xh + (size_t)b * Nq * Cin;

    for (int ct = 0; ct < 8; ct++) {
        int c0 = ct * 32;
#pragma unroll
        for (int i = 0; i < 4; i++)
            t[ty + 8 * i][tx] = p1b[(size_t)(c0 + ty + 8 * i) * Nq + n0 + tx];
        __syncthreads();
#pragma unroll
        for (int i = 0; i < 4; i++) {
            int n = n0 + ty + 8 * i;
            xo[(size_t)n * Cin + c0 + tx] = __float2half_rn(t[tx][ty + 8 * i]);
        }
        __syncthreads();
    }
    const float* p2tb = g_p2t + (size_t)b * Sq * 256;
    for (int nn = 0; nn < 32; nn++) {
        size_t base = ((size_t)b * Nq + n0 + nn) * 3;
        int   j0 = g_idx3[base], j1 = g_idx3[base + 1], j2 = g_idx3[base + 2];
        float w0 = g_w3[base], w1 = g_w3[base + 1], w2 = g_w3[base + 2];
        float v = w0 * p2tb[(size_t)j0 * 256 + tid]
                + w1 * p2tb[(size_t)j1 * 256 + tid]
                + w2 * p2tb[(size_t)j2 * 256 + tid];
        xo[(size_t)(n0 + nn) * Cin + 256 + tid] = __float2half_rn(v);
    }
}

// ---------------- weight fp32 -> fp16 ----------------------------------------
__global__ void wconv(const float* __restrict__ w, __half* __restrict__ h, int n) {
    int i = blockIdx.x * 256 + threadIdx.x;
    if (i >= n) return;
    h[i] = __float2half_rn(w[i]);
}

// ---------------- fp16 GEMM, 128x256 CTA / 64x64 warptile --------------------
// D[o,n] = sum_c W[o,c] * X[n,c];  Y fp32 [B,N,O] + per-CTA BN partials.
__global__ __launch_bounds__(256, 1)
void gemm_mma(const __half* __restrict__ Wh, const __half* __restrict__ Xh,
              float* __restrict__ Y, int O) {
    extern __shared__ char smem[];
    const int tid  = threadIdx.x;
    const int wid  = tid >> 5;
    const int lane = tid & 31;
    const int b     = blockIdx.z;
    const int nBase = blockIdx.x * NTt;
    const int oBase = blockIdx.y * MTt;
    const uint32_t sb = smem_u32(smem);
    const __half* Xb = Xh + (size_t)b * Nq * Cin;

    const int wm0 = (wid & 1) * 64;     // o
    const int wn0 = (wid >> 1) * 64;    // n

    float acc[32][4];                   // [mi*8 + ni][4]
#pragma unroll
    for (int i = 0; i < 32; i++)
#pragma unroll
        for (int j = 0; j < 4; j++) acc[i][j] = 0.0f;

    auto load_chunk = [&](int kt, int s) {
        uint32_t st = sb + s * STG;
#pragma unroll
        for (int i = 0; i < 2; i++) {   // A: 128 rows x 64B
            int idx = tid + i * 256;
            int row = idx >> 2, c = idx & 3;
            uint32_t sw = SW64((uint32_t)(row * 64 + c * 16));
            CP_ASYNC16(st + sw, Wh + (size_t)(oBase + row) * Cin + kt + c * 8);
        }
#pragma unroll
        for (int i = 0; i < 4; i++) {   // B: 256 rows x 64B
            int idx = tid + i * 256;
            int row = idx >> 2, c = idx & 3;
            uint32_t sw = SW64((uint32_t)(row * 64 + c * 16));
            CP_ASYNC16(st + B_OFF + sw,
                       Xb + (size_t)(nBase + row) * Cin + kt + c * 8);
        }
    };

    const int q  = lane >> 3, lr = lane & 7;
    const int a_row_off  = (q & 1) * 8 + lr;   // A x4: t0(k lo) t1(k hi) per m16
    const int a_col_byte = (q >> 1) * 16;
    const int b_row_off  = (q >> 1) * 8 + lr;  // B x4: t0/t1 = n tile, t2/t3 = n+8
    const int b_col_byte = (q & 1) * 16;

    load_chunk(0, 0);  CP_COMMIT();
    load_chunk(KC, 1); CP_COMMIT();

    for (int k = 0; k < NCH; k++) {
        if (k < NCH - 1) { CP_WAIT(1); } else { CP_WAIT(0); }
        __syncthreads();
        if (k + 2 < NCH) {
            load_chunk((k + 2) * KC, (k + 2) % 3);
            CP_COMMIT();
        }
        const int s = k % 3;
        uint32_t aAd = sb + s * STG;
        uint32_t bAd = aAd + B_OFF;

#pragma unroll
        for (int kk = 0; kk < KC; kk += 16) {
            uint32_t af[4][4];
#pragma unroll
            for (int mi = 0; mi < 4; mi++) {
                int row = wm0 + mi * 16 + a_row_off;
                uint32_t sw = SW64((uint32_t)(row * 64 + kk * 2 + a_col_byte));
                ldsm4(af[mi], aAd + sw);
            }
#pragma unroll
            for (int nj = 0; nj < 4; nj++) {         // n-tile pair (2nj, 2nj+1)
                int row = wn0 + nj * 16 + b_row_off;
                uint32_t sw = SW64((uint32_t)(row * 64 + kk * 2 + b_col_byte));
                uint32_t bf[4];                       // r0,r1: n tile; r2,r3: n+8
                ldsm4(bf, bAd + sw);
#pragma unroll
                for (int mi = 0; mi < 4; mi++) {
                    mma16816(acc[mi * 8 + 2 * nj],     af[mi], bf);
                    mma16816(acc[mi * 8 + 2 * nj + 1], af[mi], bf + 2);
                }
            }
        }
    }

    // ---- epilogue: two o-half passes through smem tile [256 n][68 o] --------
    float* tile = (float*)smem;                     // 256*68*4 = 69632 B
    float* redS = (float*)(smem + 69632);           // [16][128]
    float* redQ = (float*)(smem + 69632 + 8192);    // [16][128]

    const int o_thr = lane >> 2;
    const int n_thr = 2 * (lane & 3);
    const int nrow0 = tid >> 4;          // 0..15
    const int o4    = (tid & 15) * 4;    // 0..60
    float sS[2][4] = {}, sQ[2][4] = {};

#pragma unroll
    for (int p = 0; p < 2; p++) {
        __syncthreads();
        if ((wid & 1) == p) {
#pragma unroll
            for (int mi = 0; mi < 4; mi++) {
#pragma unroll
                for (int ni = 0; ni < 8; ni++) {
                    int o0 = mi * 16 + o_thr;
                    int n0 = wn0 + ni * 8 + n_thr;
                    float* d = acc[mi * 8 + ni];
                    tile[n0 * 68 + o0]           = d[0];
                    tile[(n0 + 1) * 68 + o0]     = d[1];
                    tile[n0 * 68 + o0 + 8]       = d[2];
                    tile[(n0 + 1) * 68 + o0 + 8] = d[3];
                }
            }
        }
        __syncthreads();
#pragma unroll
        for (int i = 0; i < 16; i++) {
            int n = nrow0 + 16 * i;
            float4 v = *(const float4*)&tile[n * 68 + o4];
            *(float4*)&Y[((size_t)b * Nq + nBase + n) * O + oBase + 64 * p + o4] = v;
            sS[p][0] += v.x; sS[p][1] += v.y; sS[p][2] += v.z; sS[p][3] += v.w;
            sQ[p][0] += v.x * v.x; sQ[p][1] += v.y * v.y;
            sQ[p][2] += v.z * v.z; sQ[p][3] += v.w * v.w;
        }
        *(float4*)&redS[nrow0 * 128 + 64 * p + o4] =
            make_float4(sS[p][0], sS[p][1], sS[p][2], sS[p][3]);
        *(float4*)&redQ[nrow0 * 128 + 64 * p + o4] =
            make_float4(sQ[p][0], sQ[p][1], sQ[p][2], sQ[p][3]);
    }
    __syncthreads();

    if (tid < 128) {
        float S = 0, Q = 0;
#pragma unroll
        for (int j = 0; j < 16; j++) {
            S += redS[j * 128 + tid];
            Q += redQ[j * 128 + tid];
        }
        int slot = b * gridDim.x + blockIdx.x;
        g_psum[(size_t)(oBase + tid) * NSLOT + slot] = S;
        g_psq [(size_t)(oBase + tid) * NSLOT + slot] = Q;
    }
}

// ---------------- BN finalize: one block per channel -------------------------
__global__ void bn_fin(const float* __restrict__ g, const float* __restrict__ beta,
                       int layer) {
    int o = blockIdx.x;
    int t = threadIdx.x;   // 256
    float s = g_psum[(size_t)o * NSLOT + t];
    float q = g_psq [(size_t)o * NSLOT + t];
    __shared__ float ss[8], qq[8];
#pragma unroll
    for (int off = 16; off; off >>= 1) {
        s += __shfl_down_sync(0xffffffffu, s, off);
        q += __shfl_down_sync(0xffffffffu, q, off);
    }
    if ((t & 31) == 0) { ss[t >> 5] = s; qq[t >> 5] = q; }
    __syncthreads();
    if (t == 0) {
        float S = 0, Q = 0;
#pragma unroll
        for (int j = 0; j < 8; j++) { S += ss[j]; Q += qq[j]; }
        const float invP = 1.0f / (float)Pq;
        float mean = S * invP;
        float var  = Q * invP - mean * mean;
        float rstd = rsqrtf(var + 1e-5f);
        float a    = g[o] * rstd;
        g_affine[layer * 512 + o] = make_float2(a, beta[o] - mean * a);
    }
}

// ---------------- BN+ReLU + fp16 convert: Y [B,N,512] -> g_Xh ---------------
__global__ void act_convert(const float* __restrict__ y, const float2* __restrict__ aff) {
    size_t i4 = (size_t)blockIdx.x * 256 + threadIdx.x;
    float4 v = ((const float4*)y)[i4];
    int o = (int)((i4 * 4) & (Cin - 1));
    float2 p0 = aff[o], p1 = aff[o + 1], p2 = aff[o + 2], p3 = aff[o + 3];
    float x0 = fmaxf(fmaf(p0.x, v.x, p0.y), 0.0f);
    float x1 = fmaxf(fmaf(p1.x, v.y, p1.y), 0.0f);
    float x2 = fmaxf(fmaf(p2.x, v.z, p2.y), 0.0f);
    float x3 = fmaxf(fmaf(p3.x, v.w, p3.y), 0.0f);
    ((__half2*)g_Xh)[2 * i4]     = __floats2half2_rn(x0, x1);
    ((__half2*)g_Xh)[2 * i4 + 1] = __floats2half2_rn(x2, x3);
}

// ---------------- final BN+ReLU + transpose to [B,256,N] ---------------------
__global__ void final_out(const float* __restrict__ y, float* __restrict__ out) {
    __shared__ float t[32][33];
    int b = blockIdx.z, n0 = blockIdx.x * 32, c0 = blockIdx.y * 32;
    int tx = threadIdx.x, ty = threadIdx.y;
    const float* yb = y + (size_t)b * Nq * 256;
    float2 ad = g_affine[2 * 512 + c0 + tx];
#pragma unroll
    for (int i = 0; i < 4; i++) {
        int n = n0 + ty + 8 * i;
        float v = yb[(size_t)n * 256 + c0 + tx];
        t[ty + 8 * i][tx] = fmaxf(fmaf(ad.x, v, ad.y), 0.0f);
    }
    __syncthreads();
#pragma unroll
    for (int i = 0; i < 4; i++)
        out[((size_t)b * 256 + c0 + ty + 8 * i) * Nq + n0 + tx] = t[tx][ty + 8 * i];
}

// ---------------- launch -----------------------------------------------------
extern "C" void kernel_launch(void* const* d_in, const int* in_sizes, int n_in,
                              void* d_out, int out_size) {
    const float* xyz1    = (const float*)d_in[0];
    const float* xyz2    = (const float*)d_in[1];
    const float* points1 = (const float*)d_in[2];
    const float* points2 = (const float*)d_in[3];
    const float* w0  = (const float*)d_in[4];
    const float* g0  = (const float*)d_in[6];
    const float* be0 = (const float*)d_in[7];
    const float* w1  = (const float*)d_in[8];
    const float* g1  = (const float*)d_in[10];
    const float* be1 = (const float*)d_in[11];
    const float* w2  = (const float*)d_in[12];
    const float* g2  = (const float*)d_in[14];
    const float* be2 = (const float*)d_in[15];
    float* out = (float*)d_out;

    __half *Wh, *Xh;
    float *Y;
    float2* affine;
    cudaGetSymbolAddress((void**)&Wh, g_Wh);
    cudaGetSymbolAddress((void**)&Xh, g_Xh);
    cudaGetSymbolAddress((void**)&Y, g_Y);
    cudaGetSymbolAddress((void**)&affine, g_affine);

    cudaFuncSetAttribute(gemm_mma, cudaFuncAttributeMaxDynamicSharedMemorySize, SMEM_TOT);

    // weight fp16 conversions
    wconv<<<(512 * 512 + 255) / 256, 256>>>(w0, Wh,          512 * 512);
    wconv<<<(512 * 512 + 255) / 256, 256>>>(w1, Wh + 262144, 512 * 512);
    wconv<<<(256 * 512 + 255) / 256, 256>>>(w2, Wh + 524288, 256 * 512);

    // geometry + interpolation + concat (fp16 [B,N,512] into g_Xh)
    transpose_p2<<<dim3(Sq / 32, 256 / 32, Bq), dim3(32, 8)>>>(points2);
    knn3_kernel<<<dim3(Nq / 128, Bq), 128>>>(xyz1, xyz2);
    interp_concat<<<dim3(Nq / 32, Bq), 256>>>(points1);

    // layer 0
    gemm_mma<<<dim3(Nq / NTt, 512 / MTt, Bq), 256, SMEM_TOT>>>(Wh, Xh, Y, 512);
    bn_fin<<<512, 256>>>(g0, be0, 0);
    act_convert<<<(Bq * Nq * Cin / 4) / 256, 256>>>(Y, affine);
    // layer 1
    gemm_mma<<<dim3(Nq / NTt, 512 / MTt, Bq), 256, SMEM_TOT>>>(Wh + 262144, Xh, Y, 512);
    bn_fin<<<512, 256>>>(g1, be1, 1);
    act_convert<<<(Bq * Nq * Cin / 4) / 256, 256>>>(Y, affine + 512);
    // layer 2
    gemm_mma<<<dim3(Nq / NTt, 256 / MTt, Bq), 256, SMEM_TOT>>>(Wh + 524288, Xh, Y, 256);
    bn_fin<<<256, 256>>>(g2, be2, 2);
    final_out<<<dim3(Nq / 32, 8, Bq), dim3(32, 8)>>>(Y, out);
}

// round 10
// speedup vs baseline: 1.9084x; 1.2085x over previous
#include <cuda_runtime.h>
#include <cuda_fp16.h>
#include <cstdint>
#include <math_constants.h>

#define Bq   8
#define Nq   8192
#define Sq   2048
#define Cin  512
#define NTt  128          // n-tile per CTA
#define MTt  128          // o-tile per CTA
#define KC   32           // k chunk
#define NCH  (Cin / KC)   // 16
#define NSLOT 512         // grid.x(64) * B(8)
#define Pq   (Bq * Nq)

// SMEM: 3 stages x [A 8K | B 8K] = 49152.
// Epilogue overlays: tile[128][132] (67584) + redS/redQ (8K) -> SMEM_TOT 75776.
#define STG      16384
#define B_OFF    8192
#define SMEM_TOT 75776

// ---------------- scratch (device globals) ----------------------------------
__device__ __align__(16) __half g_Xh[(size_t)Bq * Nq * Cin];     // fp16 acts
__device__ __align__(16) float  g_Y [(size_t)Bq * Nq * Cin];     // fp32 raw out
__device__ __align__(16) __half g_Wh[655360];    // w0(256K) w1(256K) w2(128K)
__device__ __align__(16) float g_p2t[(size_t)Bq * Sq * 256];
__device__ int   g_idx3[(size_t)Bq * Nq * 3];
__device__ float g_w3  [(size_t)Bq * Nq * 3];
__device__ float g_psum[512 * NSLOT];
__device__ float g_psq [512 * NSLOT];
__device__ __align__(16) float2 g_affine[3 * 512];   // (scale, shift)

// ---------------- helpers ----------------------------------------------------
__device__ __forceinline__ uint32_t smem_u32(const void* p) {
    uint32_t a;
    asm("{ .reg .u64 t; cvta.to.shared.u64 t, %1; cvt.u32.u64 %0, t; }"
        : "=r"(a) : "l"(p));
    return a;
}
#define SW64(off) ((off) ^ (((off) >> 3) & 0x30))
#define CP_ASYNC16(dst, src) \
    asm volatile("cp.async.cg.shared.global [%0], [%1], 16;" \
                 :: "r"(dst), "l"(src) : "memory")
#define CP_COMMIT()  asm volatile("cp.async.commit_group;" ::: "memory")
#define CP_WAIT(n)   asm volatile("cp.async.wait_group %0;" :: "n"(n) : "memory")

__device__ __forceinline__ void ldsm4(uint32_t* r, uint32_t addr) {
    asm volatile("ldmatrix.sync.aligned.m8n8.x4.shared.b16 {%0,%1,%2,%3}, [%4];"
                 : "=r"(r[0]), "=r"(r[1]), "=r"(r[2]), "=r"(r[3]) : "r"(addr));
}
__device__ __forceinline__ void mma16816(float* d, const uint32_t* a, const uint32_t* b) {
    asm volatile("mma.sync.aligned.m16n8k16.row.col.f32.f16.f16.f32 "
                 "{%0,%1,%2,%3}, {%4,%5,%6,%7}, {%8,%9}, {%0,%1,%2,%3};"
                 : "+f"(d[0]), "+f"(d[1]), "+f"(d[2]), "+f"(d[3])
                 : "r"(a[0]), "r"(a[1]), "r"(a[2]), "r"(a[3]),
                   "r"(b[0]), "r"(b[1]));
}

// ---------------- transpose points2: [B,D2,S] -> [B,S,D2] -------------------
__global__ void transpose_p2(const float* __restrict__ p2) {
    __shared__ float t[32][33];
    int b  = blockIdx.z;
    int s0 = blockIdx.x * 32;
    int d0 = blockIdx.y * 32;
    int tx = threadIdx.x, ty = threadIdx.y;
    const float* src = p2 + (size_t)b * 256 * Sq;
    float*       dst = g_p2t + (size_t)b * Sq * 256;
#pragma unroll
    for (int i = 0; i < 4; i++)
        t[ty + i * 8][tx] = src[(size_t)(d0 + ty + i * 8) * Sq + s0 + tx];
    __syncthreads();
#pragma unroll
    for (int i = 0; i < 4; i++)
        dst[(size_t)(s0 + ty + i * 8) * 256 + d0 + tx] = t[tx][ty + i * 8];
}

// ---------------- 3-NN + inverse-distance weights ----------------------------
__global__ void knn3_kernel(const float* __restrict__ xyz1, const float* __restrict__ xyz2) {
    __shared__ float4 sp[Sq];
    int b   = blockIdx.y;
    int tid = threadIdx.x;
    const float* x2 = xyz2 + (size_t)b * 3 * Sq;
    for (int s = tid; s < Sq; s += 128) {
        float X = x2[s], Y = x2[Sq + s], Z = x2[2 * Sq + s];
        sp[s] = make_float4(X, Y, Z, X * X + Y * Y + Z * Z);
    }
    __syncthreads();
    int n = blockIdx.x * 128 + tid;
    const float* x1 = xyz1 + (size_t)b * 3 * Nq;
    float px = x1[n], py = x1[Nq + n], pz = x1[2 * Nq + n];
    float pn = px * px + py * py + pz * pz;
    float d1 = CUDART_INF_F, d2 = CUDART_INF_F, d3 = CUDART_INF_F;
    int   i1 = 0, i2 = 0, i3 = 0;
    for (int s = 0; s < Sq; s++) {
        float4 c = sp[s];
        float dot = px * c.x + py * c.y + pz * c.z;
        float d   = pn + c.w - 2.0f * dot;
        if (d < d3) {
            if (d < d2) {
                if (d < d1) { d3 = d2; i3 = i2; d2 = d1; i2 = i1; d1 = d; i1 = s; }
                else        { d3 = d2; i3 = i2; d2 = d;  i2 = s; }
            } else          { d3 = d;  i3 = s; }
        }
    }
    float r1 = 1.0f / (d1 + 1e-8f);
    float r2 = 1.0f / (d2 + 1e-8f);
    float r3 = 1.0f / (d3 + 1e-8f);
    float rs = r1 + r2 + r3;
    size_t base = ((size_t)b * Nq + n) * 3;
    g_idx3[base] = i1; g_idx3[base + 1] = i2; g_idx3[base + 2] = i3;
    g_w3[base] = r1 / rs; g_w3[base + 1] = r2 / rs; g_w3[base + 2] = r3 / rs;
}

// ---------------- interpolate + concat -> fp16 [B,N,512] ---------------------
__global__ void interp_concat(const float* __restrict__ p1) {
    __shared__ float t[32][33];
    int b   = blockIdx.y;
    int n0  = blockIdx.x * 32;
    int tid = threadIdx.x;
    int tx  = tid & 31, ty = tid >> 5;
    const float* p1b = p1 + (size_t)b * 256 * Nq;
    __half* xo = g_Xh + (size_t)b * Nq * Cin;

    for (int ct = 0; ct < 8; ct++) {
        int c0 = ct * 32;
#pragma unroll
        for (int i = 0; i < 4; i++)
            t[ty + 8 * i][tx] = p1b[(size_t)(c0 + ty + 8 * i) * Nq + n0 + tx];
        __syncthreads();
#pragma unroll
        for (int i = 0; i < 4; i++) {
            int n = n0 + ty + 8 * i;
            xo[(size_t)n * Cin + c0 + tx] = __float2half_rn(t[tx][ty + 8 * i]);
        }
        __syncthreads();
    }
    const float* p2tb = g_p2t + (size_t)b * Sq * 256;
    for (int nn = 0; nn < 32; nn++) {
        size_t base = ((size_t)b * Nq + n0 + nn) * 3;
        int   j0 = g_idx3[base], j1 = g_idx3[base + 1], j2 = g_idx3[base + 2];
        float w0 = g_w3[base], w1 = g_w3[base + 1], w2 = g_w3[base + 2];
        float v = w0 * p2tb[(size_t)j0 * 256 + tid]
                + w1 * p2tb[(size_t)j1 * 256 + tid]
                + w2 * p2tb[(size_t)j2 * 256 + tid];
        xo[(size_t)(n0 + nn) * Cin + 256 + tid] = __float2half_rn(v);
    }
}

// ---------------- weight fp32 -> fp16 ----------------------------------------
__global__ void wconv(const float* __restrict__ w, __half* __restrict__ h, int n) {
    int i = blockIdx.x * 256 + threadIdx.x;
    if (i >= n) return;
    h[i] = __float2half_rn(w[i]);
}

// ---------------- fp16 GEMM, 128x128 CTA / 64x32 warptile, occ 2 -------------
// D[o,n] = sum_c W[o,c] * X[n,c];  Y fp32 [B,N,O] + per-CTA BN partials.
__global__ __launch_bounds__(256, 2)
void gemm_mma(const __half* __restrict__ Wh, const __half* __restrict__ Xh,
              float* __restrict__ Y, int O) {
    extern __shared__ char smem[];
    const int tid  = threadIdx.x;
    const int wid  = tid >> 5;
    const int lane = tid & 31;
    const int b     = blockIdx.z;
    const int nBase = blockIdx.x * NTt;
    const int oBase = blockIdx.y * MTt;
    const uint32_t sb = smem_u32(smem);
    const __half* Xb = Xh + (size_t)b * Nq * Cin;

    const int wm0 = (wid >> 2) * 64;   // o
    const int wn0 = (wid & 3) * 32;    // n

    float acc[16][4];
#pragma unroll
    for (int i = 0; i < 16; i++)
#pragma unroll
        for (int j = 0; j < 4; j++) acc[i][j] = 0.0f;

    auto load_chunk = [&](int kt, int s) {
        uint32_t st = sb + s * STG;
#pragma unroll
        for (int i = 0; i < 2; i++) {
            int idx = tid + i * 256;
            int row = idx >> 2, c = idx & 3;
            uint32_t sw = SW64((uint32_t)(row * 64 + c * 16));
            CP_ASYNC16(st + sw, Wh + (size_t)(oBase + row) * Cin + kt + c * 8);
            CP_ASYNC16(st + B_OFF + sw,
                       Xb + (size_t)(nBase + row) * Cin + kt + c * 8);
        }
    };

    const int q  = lane >> 3, lr = lane & 7;
    const int a_row_off  = (q & 1) * 8 + lr;   // A x4: m16 x k16 (4 tiles)
    const int a_col_byte = (q >> 1) * 16;
    const int b_row_off  = (q >> 1) * 8 + lr;  // B x4: t0/t1 = n tile, t2/t3 = n+8
    const int b_col_byte = (q & 1) * 16;

    load_chunk(0, 0);  CP_COMMIT();
    load_chunk(KC, 1); CP_COMMIT();

    for (int k = 0; k < NCH; k++) {
        if (k < NCH - 1) { CP_WAIT(1); } else { CP_WAIT(0); }
        __syncthreads();
        if (k + 2 < NCH) {
            load_chunk((k + 2) * KC, (k + 2) % 3);
            CP_COMMIT();
        }
        const int s = k % 3;
        uint32_t aAd = sb + s * STG;
        uint32_t bAd = aAd + B_OFF;

#pragma unroll
        for (int kk = 0; kk < KC; kk += 16) {
            uint32_t af[4][4];
#pragma unroll
            for (int mi = 0; mi < 4; mi++) {
                int row = wm0 + mi * 16 + a_row_off;
                uint32_t sw = SW64((uint32_t)(row * 64 + kk * 2 + a_col_byte));
                ldsm4(af[mi], aAd + sw);
            }
#pragma unroll
            for (int nj = 0; nj < 2; nj++) {         // n-tile pair (2nj, 2nj+1)
                int row = wn0 + nj * 16 + b_row_off;
                uint32_t sw = SW64((uint32_t)(row * 64 + kk * 2 + b_col_byte));
                uint32_t bf[4];                       // r0,r1: n tile; r2,r3: n+8
                ldsm4(bf, bAd + sw);
#pragma unroll
                for (int mi = 0; mi < 4; mi++) {
                    mma16816(acc[mi * 4 + 2 * nj],     af[mi], bf);
                    mma16816(acc[mi * 4 + 2 * nj + 1], af[mi], bf + 2);
                }
            }
        }
    }
    __syncthreads();   // protect smem reuse below

    // ---- epilogue: stage tile through SMEM, coalesced store + BN partials ----
    float* tile = (float*)smem;                    // [128][132] = 67584 B
    float* redS = (float*)(smem + 67584);          // [8][128]
    float* redQ = (float*)(smem + 71680);          // [8][128]

    const int o_thr = lane >> 2;
    const int n_thr = 2 * (lane & 3);
#pragma unroll
    for (int mi = 0; mi < 4; mi++) {
#pragma unroll
        for (int ni = 0; ni < 4; ni++) {
            int o0 = wm0 + mi * 16 + o_thr;
            int n0 = wn0 + ni * 8 + n_thr;
            float* d = acc[mi * 4 + ni];
            tile[n0 * 132 + o0]           = d[0];
            tile[(n0 + 1) * 132 + o0]     = d[1];
            tile[n0 * 132 + o0 + 8]       = d[2];
            tile[(n0 + 1) * 132 + o0 + 8] = d[3];
        }
    }
    __syncthreads();

    const int jrow = tid >> 5;
    const int o4   = (tid & 31) * 4;
    float s0 = 0, s1 = 0, s2 = 0, s3 = 0;
    float q0 = 0, q1 = 0, q2 = 0, q3 = 0;
#pragma unroll
    for (int i = 0; i < 16; i++) {
        int n = jrow + i * 8;
        float4 v = *(const float4*)&tile[n * 132 + o4];
        *(float4*)&Y[((size_t)b * Nq + nBase + n) * O + oBase + o4] = v;
        s0 += v.x; s1 += v.y; s2 += v.z; s3 += v.w;
        q0 += v.x * v.x; q1 += v.y * v.y; q2 += v.z * v.z; q3 += v.w * v.w;
    }
    *(float4*)&redS[jrow * 128 + o4] = make_float4(s0, s1, s2, s3);
    *(float4*)&redQ[jrow * 128 + o4] = make_float4(q0, q1, q2, q3);
    __syncthreads();

    if (tid < 128) {
        float S = 0, Q = 0;
#pragma unroll
        for (int j = 0; j < 8; j++) {
            S += redS[j * 128 + tid];
            Q += redQ[j * 128 + tid];
        }
        int slot = b * gridDim.x + blockIdx.x;
        g_psum[(size_t)(oBase + tid) * NSLOT + slot] = S;
        g_psq [(size_t)(oBase + tid) * NSLOT + slot] = Q;
    }
}

// ---------------- BN finalize: one block per channel -------------------------
__global__ void bn_fin(const float* __restrict__ g, const float* __restrict__ beta,
                       int layer) {
    int o = blockIdx.x;
    int t = threadIdx.x;   // 256
    float s = g_psum[(size_t)o * NSLOT + t] + g_psum[(size_t)o * NSLOT + t + 256];
    float q = g_psq [(size_t)o * NSLOT + t] + g_psq [(size_t)o * NSLOT + t + 256];
    __shared__ float ss[8], qq[8];
#pragma unroll
    for (int off = 16; off; off >>= 1) {
        s += __shfl_down_sync(0xffffffffu, s, off);
        q += __shfl_down_sync(0xffffffffu, q, off);
    }
    if ((t & 31) == 0) { ss[t >> 5] = s; qq[t >> 5] = q; }
    __syncthreads();
    if (t == 0) {
        float S = 0, Q = 0;
#pragma unroll
        for (int j = 0; j < 8; j++) { S += ss[j]; Q += qq[j]; }
        const float invP = 1.0f / (float)Pq;
        float mean = S * invP;
        float var  = Q * invP - mean * mean;
        float rstd = rsqrtf(var + 1e-5f);
        float a    = g[o] * rstd;
        g_affine[layer * 512 + o] = make_float2(a, beta[o] - mean * a);
    }
}

// ---------------- BN+ReLU + fp16 convert: Y [B,N,512] -> g_Xh ---------------
__global__ void act_convert(const float* __restrict__ y, const float2* __restrict__ aff) {
    size_t i4 = (size_t)blockIdx.x * 256 + threadIdx.x;
    float4 v = ((const float4*)y)[i4];
    int o = (int)((i4 * 4) & (Cin - 1));
    float2 p0 = aff[o], p1 = aff[o + 1], p2 = aff[o + 2], p3 = aff[o + 3];
    float x0 = fmaxf(fmaf(p0.x, v.x, p0.y), 0.0f);
    float x1 = fmaxf(fmaf(p1.x, v.y, p1.y), 0.0f);
    float x2 = fmaxf(fmaf(p2.x, v.z, p2.y), 0.0f);
    float x3 = fmaxf(fmaf(p3.x, v.w, p3.y), 0.0f);
    ((__half2*)g_Xh)[2 * i4]     = __floats2half2_rn(x0, x1);
    ((__half2*)g_Xh)[2 * i4 + 1] = __floats2half2_rn(x2, x3);
}

// ---------------- final BN+ReLU + transpose to [B,256,N] ---------------------
__global__ void final_out(const float* __restrict__ y, float* __restrict__ out) {
    __shared__ float t[32][33];
    int b = blockIdx.z, n0 = blockIdx.x * 32, c0 = blockIdx.y * 32;
    int tx = threadIdx.x, ty = threadIdx.y;
    const float* yb = y + (size_t)b * Nq * 256;
    float2 ad = g_affine[2 * 512 + c0 + tx];
#pragma unroll
    for (int i = 0; i < 4; i++) {
        int n = n0 + ty + 8 * i;
        float v = yb[(size_t)n * 256 + c0 + tx];
        t[ty + 8 * i][tx] = fmaxf(fmaf(ad.x, v, ad.y), 0.0f);
    }
    __syncthreads();
#pragma unroll
    for (int i = 0; i < 4; i++)
        out[((size_t)b * 256 + c0 + ty + 8 * i) * Nq + n0 + tx] = t[tx][ty + 8 * i];
}

// ---------------- launch -----------------------------------------------------
extern "C" void kernel_launch(void* const* d_in, const int* in_sizes, int n_in,
                              void* d_out, int out_size) {
    const float* xyz1    = (const float*)d_in[0];
    const float* xyz2    = (const float*)d_in[1];
    const float* points1 = (const float*)d_in[2];
    const float* points2 = (const float*)d_in[3];
    const float* w0  = (const float*)d_in[4];
    const float* g0  = (const float*)d_in[6];
    const float* be0 = (const float*)d_in[7];
    const float* w1  = (const float*)d_in[8];
    const float* g1  = (const float*)d_in[10];
    const float* be1 = (const float*)d_in[11];
    const float* w2  = (const float*)d_in[12];
    const float* g2  = (const float*)d_in[14];
    const float* be2 = (const float*)d_in[15];
    float* out = (float*)d_out;

    __half *Wh, *Xh;
    float *Y;
    float2* affine;
    cudaGetSymbolAddress((void**)&Wh, g_Wh);
    cudaGetSymbolAddress((void**)&Xh, g_Xh);
    cudaGetSymbolAddress((void**)&Y, g_Y);
    cudaGetSymbolAddress((void**)&affine, g_affine);

    cudaFuncSetAttribute(gemm_mma, cudaFuncAttributeMaxDynamicSharedMemorySize, SMEM_TOT);

    // weight fp16 conversions
    wconv<<<(512 * 512 + 255) / 256, 256>>>(w0, Wh,          512 * 512);
    wconv<<<(512 * 512 + 255) / 256, 256>>>(w1, Wh + 262144, 512 * 512);
    wconv<<<(256 * 512 + 255) / 256, 256>>>(w2, Wh + 524288, 256 * 512);

    // geometry + interpolation + concat (fp16 [B,N,512] into g_Xh)
    transpose_p2<<<dim3(Sq / 32, 256 / 32, Bq), dim3(32, 8)>>>(points2);
    knn3_kernel<<<dim3(Nq / 128, Bq), 128>>>(xyz1, xyz2);
    interp_concat<<<dim3(Nq / 32, Bq), 256>>>(points1);

    // layer 0
    gemm_mma<<<dim3(Nq / NTt, 512 / MTt, Bq), 256, SMEM_TOT>>>(Wh, Xh, Y, 512);
    bn_fin<<<512, 256>>>(g0, be0, 0);
    act_convert<<<(Bq * Nq * Cin / 4) / 256, 256>>>(Y, affine);
    // layer 1
    gemm_mma<<<dim3(Nq / NTt, 512 / MTt, Bq), 256, SMEM_TOT>>>(Wh + 262144, Xh, Y, 512);
    bn_fin<<<512, 256>>>(g1, be1, 1);
    act_convert<<<(Bq * Nq * Cin / 4) / 256, 256>>>(Y, affine + 512);
    // layer 2
    gemm_mma<<<dim3(Nq / NTt, 256 / MTt, Bq), 256, SMEM_TOT>>>(Wh + 524288, Xh, Y, 256);
    bn_fin<<<256, 256>>>(g2, be2, 2);
    final_out<<<dim3(Nq / 32, 8, Bq), dim3(32, 8)>>>(Y, out);
}